// round 7
// baseline (speedup 1.0000x reference)
#include <cuda_runtime.h>
#include <cuda_bf16.h>
#include <cstdint>

#define CH 128
#define NB 8
#define SP 16384              // spatial = 128*128
#define BSTRIDE (CH*SP)
#define GROUPS 8
#define GSIZE 16
#define HEADS 8
#define HD 16
#define EPS 1e-5f

typedef unsigned long long u64;

// packed fp32x2 helpers (scalar syrk path)
__device__ __forceinline__ u64 pack2(float lo, float hi) {
    u64 r; asm("mov.b64 %0, {%1,%2};" : "=l"(r) : "f"(lo), "f"(hi)); return r;
}
__device__ __forceinline__ void fma2(u64& d, u64 a, u64 b) {
    asm("fma.rn.f32x2 %0, %1, %2, %0;" : "+l"(d) : "l"(a), "l"(b));
}
__device__ __forceinline__ float2 unpack2(u64 v) {
    float2 f; asm("mov.b64 {%0,%1}, %2;" : "=f"(f.x), "=f"(f.y) : "l"(v)); return f;
}

// -------- device scratch (no allocs allowed) --------
__device__ float g_S[NB][CH][CH];
__device__ float g_r[NB][CH];
__device__ float g_alpha[NB][CH];
__device__ float g_Bp[NB][CH];
__device__ float g_u[NB][CH];
__device__ float g_M[NB][CH][CH];
__device__ __align__(16) __nv_bfloat16 g_Ahi[NB][CH*CH];  // (C+I)[o][c] hi
__device__ __align__(16) __nv_bfloat16 g_Alo[NB][CH*CH];  // (C+I)[o][c] lo
__device__ float g_d[NB][CH];

// -------- zero scratch --------
__global__ void k_zero() {
    int idx = blockIdx.x * blockDim.x + threadIdx.x;
    if (idx < NB*CH*CH) ((float*)g_S)[idx] = 0.f;
    if (idx < NB*CH)    ((float*)g_r)[idx] = 0.f;
}

// -------- kernel 1: per-batch syrk S = X X^T (upper tiles) + row sums --------
__global__ __launch_bounds__(128) void k_syrk(const float* __restrict__ x) {
    int b = blockIdx.z;
    int tile = blockIdx.x;
    int ti = (tile == 2) ? 1 : 0;
    int tj = (tile == 0) ? 0 : 1;
    int arow0 = ti * 64, brow0 = tj * 64;
    int s0 = blockIdx.y * 1024;
    bool diag = (ti == tj);

    __shared__ __align__(16) float As[16][68];
    __shared__ __align__(16) float Bs[16][68];

    int t = threadIdx.x;
    int r = t >> 1, q = t & 1;
    int tx = t & 15, ty = t >> 4;

    u64 acc2[4][4];
    #pragma unroll
    for (int p = 0; p < 4; ++p)
        #pragma unroll
        for (int j = 0; j < 4; ++j) acc2[p][j] = 0ull;
    float rsum = 0.f;

    const float* xb = x + (size_t)b * BSTRIDE;
    const float* pa = xb + (arow0 + r) * SP + s0 + 8 * q;
    const float* pb = xb + (brow0 + r) * SP + s0 + 8 * q;

    float4 av0 = *(const float4*)(pa + 0);
    float4 av1 = *(const float4*)(pa + 4);
    float4 bv0 = *(const float4*)(pb + 0);
    float4 bv1 = *(const float4*)(pb + 4);

    for (int ch = 0; ch < 64; ++ch) {
        __syncthreads();
        int c0 = 8 * q;
        As[c0+0][r] = av0.x; As[c0+1][r] = av0.y; As[c0+2][r] = av0.z; As[c0+3][r] = av0.w;
        As[c0+4][r] = av1.x; As[c0+5][r] = av1.y; As[c0+6][r] = av1.z; As[c0+7][r] = av1.w;
        Bs[c0+0][r] = bv0.x; Bs[c0+1][r] = bv0.y; Bs[c0+2][r] = bv0.z; Bs[c0+3][r] = bv0.w;
        Bs[c0+4][r] = bv1.x; Bs[c0+5][r] = bv1.y; Bs[c0+6][r] = bv1.z; Bs[c0+7][r] = bv1.w;
        if (diag) rsum += av0.x + av0.y + av0.z + av0.w + av1.x + av1.y + av1.z + av1.w;
        __syncthreads();
        if (ch < 63) {
            const float* na = pa + (ch + 1) * 16;
            const float* nb = pb + (ch + 1) * 16;
            av0 = *(const float4*)(na + 0);
            av1 = *(const float4*)(na + 4);
            bv0 = *(const float4*)(nb + 0);
            bv1 = *(const float4*)(nb + 4);
        }
        #pragma unroll
        for (int k = 0; k < 16; ++k) {
            u64 a0 = *(const u64*)&As[k][8*ty + 0];
            u64 a1 = *(const u64*)&As[k][8*ty + 2];
            u64 a2 = *(const u64*)&As[k][8*ty + 4];
            u64 a3 = *(const u64*)&As[k][8*ty + 6];
            float4 bv = *(const float4*)&Bs[k][4*tx];
            u64 bb0 = pack2(bv.x, bv.x);
            u64 bb1 = pack2(bv.y, bv.y);
            u64 bb2 = pack2(bv.z, bv.z);
            u64 bb3 = pack2(bv.w, bv.w);
            fma2(acc2[0][0], a0, bb0); fma2(acc2[0][1], a0, bb1);
            fma2(acc2[0][2], a0, bb2); fma2(acc2[0][3], a0, bb3);
            fma2(acc2[1][0], a1, bb0); fma2(acc2[1][1], a1, bb1);
            fma2(acc2[1][2], a1, bb2); fma2(acc2[1][3], a1, bb3);
            fma2(acc2[2][0], a2, bb0); fma2(acc2[2][1], a2, bb1);
            fma2(acc2[2][2], a2, bb2); fma2(acc2[2][3], a2, bb3);
            fma2(acc2[3][0], a3, bb0); fma2(acc2[3][1], a3, bb1);
            fma2(acc2[3][2], a3, bb2); fma2(acc2[3][3], a3, bb3);
        }
    }
    #pragma unroll
    for (int p = 0; p < 4; ++p)
        #pragma unroll
        for (int j = 0; j < 4; ++j) {
            float2 v = unpack2(acc2[p][j]);
            atomicAdd(&g_S[b][arow0 + 8*ty + 2*p + 0][brow0 + 4*tx + j], v.x);
            atomicAdd(&g_S[b][arow0 + 8*ty + 2*p + 1][brow0 + 4*tx + j], v.y);
        }
    if (diag) atomicAdd(&g_r[b][arow0 + r], rsum);
}

// -------- prep1 --------
__global__ __launch_bounds__(128) void k_prep1(const float* __restrict__ gn_w,
                                               const float* __restrict__ gn_b,
                                               const float* __restrict__ w_in,
                                               const float* __restrict__ b_in) {
    int b = blockIdx.x;
    int t = threadIdx.x;
    __shared__ float r_s[CH], sq_s[CH], alpha_s[CH], beta_s[CH];
    r_s[t]  = g_r[b][t];
    sq_s[t] = g_S[b][t][t];
    __syncthreads();
    int g0 = (t >> 4) << 4;
    float sum = 0.f, sumsq = 0.f;
    #pragma unroll
    for (int i = 0; i < GSIZE; ++i) { sum += r_s[g0 + i]; sumsq += sq_s[g0 + i]; }
    const float inv_cnt = 1.f / (float)(GSIZE * SP);
    float mu  = sum * inv_cnt;
    float var = sumsq * inv_cnt - mu * mu;
    float al = gn_w[t] * rsqrtf(var + EPS);
    float be = gn_b[t] - mu * al;
    alpha_s[t] = al; beta_s[t] = be;
    g_alpha[b][t] = al;
    __syncthreads();
    float bp = b_in[t], uu = 0.f;
    const float* wrow = w_in + t * CH;
    for (int c = 0; c < CH; ++c) {
        float w = wrow[c];
        bp += w * beta_s[c];
        uu += w * alpha_s[c] * r_s[c];
    }
    g_Bp[b][t] = bp;
    g_u[b][t]  = uu;
    for (int idx = t; idx < 64 * 64; idx += 128) {
        int i = idx >> 6, j = idx & 63;
        g_S[b][64 + i][j] = g_S[b][j][64 + i];
    }
}

// -------- prep2 --------
#define SSTR 132
#define SMEM_P2 ((CH*SSTR + 2*16*SSTR + 2*16*17) * 4)
__global__ __launch_bounds__(512) void k_prep2(const float* __restrict__ w_in,
                                               const float* __restrict__ w_out) {
    extern __shared__ float sm2[];
    float* Ss  = sm2;
    float* Whs = Ss + CH * SSTR;
    float* Ts  = Whs + 16 * SSTR;
    float* sc  = Ts + 16 * SSTR;
    float* Wt  = sc + 16 * 17;

    int b = blockIdx.x >> 3, h = blockIdx.x & 7;
    int t = threadIdx.x;

    {
        const float4* src = (const float4*)&g_S[b][0][0];
        for (int idx = t; idx < CH * CH / 4; idx += 512) {
            int row = idx >> 5, c4 = idx & 31;
            *(float4*)&Ss[row * SSTR + 4 * c4] = src[idx];
        }
    }
    for (int idx = t; idx < 16 * CH; idx += 512) {
        int i = idx >> 7, k = idx & 127;
        Whs[i * SSTR + k] = w_in[(h * 16 + i) * CH + k] * g_alpha[b][k];
    }
    __syncthreads();

    {
        int l = t >> 2, ihb = (t & 3) * 4;
        float ta[4];
        #pragma unroll
        for (int i = 0; i < 4; ++i) ta[i] = 0.f;
        for (int k4 = 0; k4 < 32; ++k4) {
            float4 sv = *(const float4*)&Ss[l * SSTR + 4 * k4];
            #pragma unroll
            for (int i = 0; i < 4; ++i) {
                float4 wv = *(const float4*)&Whs[(ihb + i) * SSTR + 4 * k4];
                ta[i] += wv.x * sv.x + wv.y * sv.y + wv.z * sv.z + wv.w * sv.w;
            }
        }
        #pragma unroll
        for (int i = 0; i < 4; ++i) Ts[(ihb + i) * SSTR + l] = ta[i];
    }
    __syncthreads();

    if (t < 256) {
        int i = t >> 4, j = t & 15;
        float g = 0.f;
        for (int l4 = 0; l4 < 32; ++l4) {
            float4 tv = *(const float4*)&Ts[i * SSTR + 4 * l4];
            float4 wv = *(const float4*)&Whs[j * SSTR + 4 * l4];
            g += tv.x * wv.x + tv.y * wv.y + tv.z * wv.z + tv.w * wv.w;
        }
        float ui = g_u[b][h*16 + i], bi = g_Bp[b][h*16 + i];
        float uj = g_u[b][h*16 + j], bj = g_Bp[b][h*16 + j];
        sc[i * 17 + j] = 0.25f * (g + ui*bj + bi*uj + (float)SP * bi * bj);
    }
    __syncthreads();

    if (t < 16) {
        float m = sc[t * 17 + 0];
        #pragma unroll
        for (int j = 1; j < 16; ++j) m = fmaxf(m, sc[t * 17 + j]);
        float e[16], s = 0.f;
        #pragma unroll
        for (int j = 0; j < 16; ++j) { e[j] = expf(sc[t * 17 + j] - m); s += e[j]; }
        float inv = 1.f / s;
        #pragma unroll
        for (int j = 0; j < 16; ++j) Wt[t * 17 + j] = e[j] * inv;
    }
    __syncthreads();

    {
        int o = t >> 2, jhb = (t & 3) * 4;
        float wo[16];
        #pragma unroll
        for (int i = 0; i < 16; ++i) wo[i] = w_out[o * CH + h * 16 + i];
        #pragma unroll
        for (int j = 0; j < 4; ++j) {
            float m = 0.f;
            #pragma unroll
            for (int i = 0; i < 16; ++i) m += wo[i] * Wt[i * 17 + jhb + j];
            g_M[b][o][h * 16 + jhb + j] = m;
        }
    }
}

// -------- prep3: A = (M W' + I) as bf16 hi/lo [o][c]; d = M B' + b_out --------
__global__ __launch_bounds__(128) void k_prep3(const float* __restrict__ w_in,
                                               const float* __restrict__ b_out) {
    int b = blockIdx.y, o0 = blockIdx.x * 16;
    int t = threadIdx.x;  // = c
    __shared__ float Ms[16][CH];
    __shared__ float Bp_s[CH];
    for (int idx = t; idx < 16 * CH; idx += 128) {
        int i = idx >> 7, k = idx & 127;
        Ms[i][k] = g_M[b][o0 + i][k];
    }
    Bp_s[t] = g_Bp[b][t];
    __syncthreads();
    float a[16];
    #pragma unroll
    for (int i = 0; i < 16; ++i) a[i] = 0.f;
    for (int k = 0; k < CH; ++k) {
        float wv = w_in[k * CH + t];
        #pragma unroll
        for (int i = 0; i < 16; ++i) a[i] += Ms[i][k] * wv;
    }
    float al = g_alpha[b][t];
    #pragma unroll
    for (int i = 0; i < 16; ++i) {
        float v = al * a[i];
        if (o0 + i == t) v += 1.0f;     // fold residual identity
        __nv_bfloat16 h = __float2bfloat16(v);
        float lo = v - __bfloat162float(h);
        g_Ahi[b][(o0 + i) * CH + t] = h;
        g_Alo[b][(o0 + i) * CH + t] = __float2bfloat16(lo);
    }
    if (t < 16) {
        float dv = b_out[o0 + t];
        for (int k = 0; k < CH; ++k) dv += Ms[t][k] * Bp_s[k];
        g_d[b][o0 + t] = dv;
    }
}

// ==================== main GEMM via mma.sync (HMMA, bf16 hi/lo split) ========
// out[o][s0+n] = sum_c A[o][c] * x[c][s0+n] + d[o]
// smem rows padded to 136 bf16 (272 B) -> frag LDS is bank-conflict-free.
#define ASTR2 272                     // bytes per bf16 row (136 elems)
#define A_HI_OFF 0
#define A_LO_OFF 34816
#define XT_HI_OFF 69632
#define XT_LO_OFF 104448
#define XS_OFF   139264               // fp32 staging [128][132]
#define DS_OFF   (XS_OFF + 128*132*4) // 206848
#define MM_SMEM  (DS_OFF + 512)

__device__ __forceinline__ void mma16816(float* c, uint32_t a0, uint32_t a1,
                                         uint32_t a2, uint32_t a3,
                                         uint32_t b0, uint32_t b1) {
    asm volatile("mma.sync.aligned.m16n8k16.row.col.f32.bf16.bf16.f32 "
                 "{%0,%1,%2,%3}, {%4,%5,%6,%7}, {%8,%9}, {%0,%1,%2,%3};"
                 : "+f"(c[0]), "+f"(c[1]), "+f"(c[2]), "+f"(c[3])
                 : "r"(a0), "r"(a1), "r"(a2), "r"(a3), "r"(b0), "r"(b1));
}

__global__ __launch_bounds__(256, 1) void k_main_mma(const float* __restrict__ x,
                                                     float* __restrict__ out) {
    extern __shared__ __align__(16) char smc[];
    float* xs  = (float*)(smc + XS_OFF);
    float* d_s = (float*)(smc + DS_OFF);

    int b = blockIdx.y;
    int s0 = blockIdx.x * 128;
    int t = threadIdx.x;
    int wid = t >> 5, lane = t & 31;
    int g = lane >> 2, tg = lane & 3;

    // ---- stage A hi/lo (row-major, padded 272B rows) ----
    {
        const uint4* Ah = (const uint4*)&g_Ahi[b][0];
        const uint4* Al = (const uint4*)&g_Alo[b][0];
        for (int m = t; m < 2048; m += 256) {      // 128 rows x 16 u4-chunks
            int o = m >> 4, cg = m & 15;
            uint32_t off = (uint32_t)o * ASTR2 + cg * 16;
            *(uint4*)(smc + A_HI_OFF + off) = Ah[m];
            *(uint4*)(smc + A_LO_OFF + off) = Al[m];
        }
        if (t < CH) d_s[t] = g_d[b][t];
    }
    // ---- stage x fp32 [c][128] -> xs [c][132] ----
    {
        const float* xb = x + (size_t)b * BSTRIDE + s0;
        for (int idx = t; idx < CH * 32; idx += 256) {
            int row = idx >> 5, c4 = idx & 31;
            *(float4*)&xs[row * 132 + 4 * c4] = *(const float4*)(xb + row * SP + 4 * c4);
        }
    }
    __syncthreads();

    // ---- convert + transpose: xt[s][c] bf16 hi/lo ----
    for (int m = t; m < 2048; m += 256) {
        int s = m & 127, cg = m >> 7;              // cg: 8-channel group 0..15
        int c0 = cg * 8;
        uint32_t hw[4], lw[4];
        #pragma unroll
        for (int j = 0; j < 4; ++j) {
            float f0 = xs[(c0 + 2*j) * 132 + s];
            float f1 = xs[(c0 + 2*j + 1) * 132 + s];
            __nv_bfloat16 h0 = __float2bfloat16(f0);
            __nv_bfloat16 h1 = __float2bfloat16(f1);
            float l0 = f0 - __bfloat162float(h0);
            float l1 = f1 - __bfloat162float(h1);
            __nv_bfloat162 hp; hp.x = h0; hp.y = h1;
            __nv_bfloat162 lp; lp.x = __float2bfloat16(l0); lp.y = __float2bfloat16(l1);
            hw[j] = *(uint32_t*)&hp;
            lw[j] = *(uint32_t*)&lp;
        }
        uint32_t off = (uint32_t)s * ASTR2 + c0 * 2;
        *(uint4*)(smc + XT_HI_OFF + off) = make_uint4(hw[0], hw[1], hw[2], hw[3]);
        *(uint4*)(smc + XT_LO_OFF + off) = make_uint4(lw[0], lw[1], lw[2], lw[3]);
    }
    __syncthreads();

    // ---- warp tiling: 4 m-warps x 2 n-warps; warp: 32 o x 64 s ----
    int wm = wid >> 1, wn = wid & 1;
    int m0 = wm * 32, n0 = wn * 64;

    float acc[2][8][4];
    #pragma unroll
    for (int i = 0; i < 2; ++i)
        #pragma unroll
        for (int j = 0; j < 8; ++j)
            #pragma unroll
            for (int q = 0; q < 4; ++q) acc[i][j][q] = 0.f;

    #pragma unroll 1
    for (int kk = 0; kk < 8; ++kk) {
        int k = kk * 16;
        uint32_t koff = (uint32_t)k * 2 + tg * 4;

        // B fragments: 8 n-tiles, hi & lo
        uint32_t bh[8][2], bl[8][2];
        #pragma unroll
        for (int j = 0; j < 8; ++j) {
            uint32_t roff = (uint32_t)(n0 + 8*j + g) * ASTR2 + koff;
            bh[j][0] = *(const uint32_t*)(smc + XT_HI_OFF + roff);
            bh[j][1] = *(const uint32_t*)(smc + XT_HI_OFF + roff + 16);
            bl[j][0] = *(const uint32_t*)(smc + XT_LO_OFF + roff);
            bl[j][1] = *(const uint32_t*)(smc + XT_LO_OFF + roff + 16);
        }

        #pragma unroll
        for (int i = 0; i < 2; ++i) {
            uint32_t r0off = (uint32_t)(m0 + 16*i + g) * ASTR2 + koff;
            uint32_t r1off = r0off + 8 * ASTR2;
            uint32_t ah0 = *(const uint32_t*)(smc + A_HI_OFF + r0off);
            uint32_t ah1 = *(const uint32_t*)(smc + A_HI_OFF + r1off);
            uint32_t ah2 = *(const uint32_t*)(smc + A_HI_OFF + r0off + 16);
            uint32_t ah3 = *(const uint32_t*)(smc + A_HI_OFF + r1off + 16);
            uint32_t al0 = *(const uint32_t*)(smc + A_LO_OFF + r0off);
            uint32_t al1 = *(const uint32_t*)(smc + A_LO_OFF + r1off);
            uint32_t al2 = *(const uint32_t*)(smc + A_LO_OFF + r0off + 16);
            uint32_t al3 = *(const uint32_t*)(smc + A_LO_OFF + r1off + 16);
            #pragma unroll
            for (int j = 0; j < 8; ++j) {
                mma16816(acc[i][j], ah0, ah1, ah2, ah3, bh[j][0], bh[j][1]);
                mma16816(acc[i][j], ah0, ah1, ah2, ah3, bl[j][0], bl[j][1]);
                mma16816(acc[i][j], al0, al1, al2, al3, bh[j][0], bh[j][1]);
            }
        }
    }

    // ---- epilogue: add bias, store float2 per (row, tile) ----
    float* ob = out + (size_t)b * BSTRIDE + s0;
    #pragma unroll
    for (int i = 0; i < 2; ++i) {
        int r0 = m0 + 16*i + g;
        int r1 = r0 + 8;
        float d0 = d_s[r0], d1 = d_s[r1];
        #pragma unroll
        for (int j = 0; j < 8; ++j) {
            int n = n0 + 8*j + 2*tg;
            float2 v0 = { acc[i][j][0] + d0, acc[i][j][1] + d0 };
            float2 v1 = { acc[i][j][2] + d1, acc[i][j][3] + d1 };
            *(float2*)(ob + (size_t)r0 * SP + n) = v0;
            *(float2*)(ob + (size_t)r1 * SP + n) = v1;
        }
    }
}

extern "C" void kernel_launch(void* const* d_in, const int* in_sizes, int n_in,
                              void* d_out, int out_size) {
    const float* x    = (const float*)d_in[0];
    const float* gn_w = (const float*)d_in[1];
    const float* gn_b = (const float*)d_in[2];
    const float* w_in = (const float*)d_in[3];
    const float* b_in = (const float*)d_in[4];
    const float* w_out= (const float*)d_in[5];
    const float* b_out= (const float*)d_in[6];
    float* out = (float*)d_out;
    (void)in_sizes; (void)n_in; (void)out_size;

    cudaFuncSetAttribute(k_prep2,   cudaFuncAttributeMaxDynamicSharedMemorySize, SMEM_P2);
    cudaFuncSetAttribute(k_main_mma, cudaFuncAttributeMaxDynamicSharedMemorySize, MM_SMEM);

    k_zero<<<512, 256>>>();
    dim3 gs(3, 16, NB);
    k_syrk<<<gs, 128>>>(x);
    k_prep1<<<NB, 128>>>(gn_w, gn_b, w_in, b_in);
    k_prep2<<<64, 512, SMEM_P2>>>(w_in, w_out);
    k_prep3<<<dim3(8, NB), 128>>>(w_in, b_out);
    k_main_mma<<<dim3(SP / 128, NB), 256, MM_SMEM>>>(x, out);
}

// round 8
// speedup vs baseline: 1.4498x; 1.4498x over previous
#include <cuda_runtime.h>
#include <cuda_bf16.h>
#include <cstdint>

#define CH 128
#define NB 8
#define SP 16384              // spatial = 128*128
#define BSTRIDE (CH*SP)
#define GSIZE 16
#define EPS 1e-5f

// ---------------- helpers ----------------
__device__ __forceinline__ uint32_t smem_u32(const void* p) {
    uint32_t a;
    asm("{ .reg .u64 t; cvta.to.shared.u64 t, %1; cvt.u32.u64 %0, t; }" : "=r"(a) : "l"(p));
    return a;
}
#define CP_ASYNC16(dst, src) \
    asm volatile("cp.async.cg.shared.global [%0], [%1], 16;" :: "r"(dst), "l"(src) : "memory")
#define CP_COMMIT() asm volatile("cp.async.commit_group;" ::: "memory")
#define CP_WAIT1()  asm volatile("cp.async.wait_group 1;" ::: "memory")
#define CP_WAIT0()  asm volatile("cp.async.wait_group 0;" ::: "memory")

__device__ __forceinline__ void mma16816(float* c, uint32_t a0, uint32_t a1,
                                         uint32_t a2, uint32_t a3,
                                         uint32_t b0, uint32_t b1) {
    asm volatile("mma.sync.aligned.m16n8k16.row.col.f32.bf16.bf16.f32 "
                 "{%0,%1,%2,%3}, {%4,%5,%6,%7}, {%8,%9}, {%0,%1,%2,%3};"
                 : "+f"(c[0]), "+f"(c[1]), "+f"(c[2]), "+f"(c[3])
                 : "r"(a0), "r"(a1), "r"(a2), "r"(a3), "r"(b0), "r"(b1));
}

// split two fp32 into packed bf16x2 hi and lo words
__device__ __forceinline__ void split2(float a, float b, uint32_t& hi, uint32_t& lo) {
    __nv_bfloat16 ha = __float2bfloat16(a), hb = __float2bfloat16(b);
    float la = a - __bfloat162float(ha), lb = b - __bfloat162float(hb);
    __nv_bfloat162 hp; hp.x = ha; hp.y = hb;
    __nv_bfloat162 lp; lp.x = __float2bfloat16(la); lp.y = __float2bfloat16(lb);
    hi = *(uint32_t*)&hp; lo = *(uint32_t*)&lp;
}

// ---------------- device scratch ----------------
__device__ float g_S[NB][CH][CH];
__device__ float g_r[NB][CH];
__device__ float g_alpha[NB][CH];
__device__ float g_Bp[NB][CH];
__device__ float g_u[NB][CH];
__device__ float g_M[NB][CH][CH];
__device__ __align__(16) __nv_bfloat16 g_Ahi[NB][CH*CH];  // (C+I)[o][c] hi
__device__ __align__(16) __nv_bfloat16 g_Alo[NB][CH*CH];  // (C+I)[o][c] lo
__device__ __align__(16) float g_d[NB][CH];

__global__ void k_zero() {
    int idx = blockIdx.x * blockDim.x + threadIdx.x;
    if (idx < NB*CH*CH) ((float*)g_S)[idx] = 0.f;
    if (idx < NB*CH)    ((float*)g_r)[idx] = 0.f;
}

// ================= syrk via HMMA: S = X X^T (full), + row sums =================
// grid (32, NB), 256 thr, occ 2. Chunk = 512 s (8 tiles of 64).
// Both mma operands come from the same bf16 [c][s] buffer (k = s) — no transpose.
#define SK_XH  0                         // 128 rows x 144 B (64 bf16 + pad)
#define SK_XL  18432
#define SK_XS0 36864                     // fp32 staging [128][68]
#define SK_XS1 71680
#define SK_SMEM 106496
__global__ __launch_bounds__(256, 2) void k_syrk_mma(const float* __restrict__ x) {
    extern __shared__ __align__(16) char sm[];
    uint32_t sb = smem_u32(sm);
    int b = blockIdx.y;
    int chunk0 = blockIdx.x * 512;
    int t = threadIdx.x;
    int wid = t >> 5, lane = t & 31, g = lane >> 2, tg = lane & 3;
    int m0 = (wid >> 1) * 32, n0 = (wid & 1) * 64;

    const float* xb = x + (size_t)b * BSTRIDE + chunk0;

    // prologue: cp.async tile 0 -> XS0
    #pragma unroll
    for (int w = 0; w < 8; ++w) {
        int fidx = t + 256*w;
        int c = fidx >> 4, f4 = fidx & 15;
        CP_ASYNC16(sb + SK_XS0 + (uint32_t)(c*68 + 4*f4)*4,
                   xb + (size_t)c*SP + 4*f4);
    }
    CP_COMMIT();

    float acc[2][8][4];
    #pragma unroll
    for (int i = 0; i < 2; ++i)
        #pragma unroll
        for (int j = 0; j < 8; ++j)
            #pragma unroll
            for (int q = 0; q < 4; ++q) acc[i][j][q] = 0.f;
    float rs[8];
    #pragma unroll
    for (int w = 0; w < 8; ++w) rs[w] = 0.f;

    for (int tile = 0; tile < 8; ++tile) {
        int buf = tile & 1;
        if (tile + 1 < 8) {
            int nbuf = buf ^ 1;
            #pragma unroll
            for (int w = 0; w < 8; ++w) {
                int fidx = t + 256*w;
                int c = fidx >> 4, f4 = fidx & 15;
                CP_ASYNC16(sb + (nbuf ? SK_XS1 : SK_XS0) + (uint32_t)(c*68 + 4*f4)*4,
                           xb + (size_t)c*SP + (tile+1)*64 + 4*f4);
            }
            CP_COMMIT();
            CP_WAIT1();
        } else {
            CP_WAIT0();
        }
        __syncthreads();      // staged data visible; prev mma done reading XH/XL

        // convert fp32 -> bf16 hi/lo [c][s], accumulate row sums
        const float* xsB = (const float*)(sm + (buf ? SK_XS1 : SK_XS0));
        #pragma unroll
        for (int w = 0; w < 8; ++w) {
            int fidx = t + 256*w;
            int c = fidx >> 4, f4 = fidx & 15;
            float4 v = *(const float4*)(xsB + c*68 + 4*f4);
            rs[w] += v.x + v.y + v.z + v.w;
            uint32_t h01, l01, h23, l23;
            split2(v.x, v.y, h01, l01);
            split2(v.z, v.w, h23, l23);
            uint32_t off = (uint32_t)c*144 + f4*8;
            *(uint32_t*)(sm + SK_XH + off)     = h01;
            *(uint32_t*)(sm + SK_XH + off + 4) = h23;
            *(uint32_t*)(sm + SK_XL + off)     = l01;
            *(uint32_t*)(sm + SK_XL + off + 4) = l23;
        }
        __syncthreads();

        // mma over 4 k-steps of 16 s
        #pragma unroll
        for (int k = 0; k < 4; ++k) {
            uint32_t koff = (uint32_t)k*32 + tg*4;
            uint32_t ah[2][4], al[2][4];
            #pragma unroll
            for (int i = 0; i < 2; ++i) {
                uint32_t r0 = (uint32_t)(m0 + 16*i + g)*144 + koff;
                uint32_t r1 = r0 + 8*144;
                ah[i][0] = *(const uint32_t*)(sm + SK_XH + r0);
                ah[i][1] = *(const uint32_t*)(sm + SK_XH + r1);
                ah[i][2] = *(const uint32_t*)(sm + SK_XH + r0 + 16);
                ah[i][3] = *(const uint32_t*)(sm + SK_XH + r1 + 16);
                al[i][0] = *(const uint32_t*)(sm + SK_XL + r0);
                al[i][1] = *(const uint32_t*)(sm + SK_XL + r1);
                al[i][2] = *(const uint32_t*)(sm + SK_XL + r0 + 16);
                al[i][3] = *(const uint32_t*)(sm + SK_XL + r1 + 16);
            }
            #pragma unroll
            for (int j = 0; j < 8; ++j) {
                uint32_t rb = (uint32_t)(n0 + 8*j + g)*144 + koff;
                uint32_t bh0 = *(const uint32_t*)(sm + SK_XH + rb);
                uint32_t bh1 = *(const uint32_t*)(sm + SK_XH + rb + 16);
                uint32_t bl0 = *(const uint32_t*)(sm + SK_XL + rb);
                uint32_t bl1 = *(const uint32_t*)(sm + SK_XL + rb + 16);
                #pragma unroll
                for (int i = 0; i < 2; ++i) {
                    mma16816(acc[i][j], ah[i][0], ah[i][1], ah[i][2], ah[i][3], bh0, bh1);
                    mma16816(acc[i][j], ah[i][0], ah[i][1], ah[i][2], ah[i][3], bl0, bl1);
                    mma16816(acc[i][j], al[i][0], al[i][1], al[i][2], al[i][3], bh0, bh1);
                }
            }
        }
    }

    // flush accumulators
    #pragma unroll
    for (int i = 0; i < 2; ++i)
        #pragma unroll
        for (int j = 0; j < 8; ++j) {
            int r0 = m0 + 16*i + g, r1 = r0 + 8;
            int col = n0 + 8*j + 2*tg;
            atomicAdd(&g_S[b][r0][col],     acc[i][j][0]);
            atomicAdd(&g_S[b][r0][col + 1], acc[i][j][1]);
            atomicAdd(&g_S[b][r1][col],     acc[i][j][2]);
            atomicAdd(&g_S[b][r1][col + 1], acc[i][j][3]);
        }
    #pragma unroll
    for (int w = 0; w < 8; ++w)
        atomicAdd(&g_r[b][(t >> 4) + 16*w], rs[w]);
}

// ================= prep1: GN stats, alpha/beta, B', u =================
__global__ __launch_bounds__(128) void k_prep1(const float* __restrict__ gn_w,
                                               const float* __restrict__ gn_b,
                                               const float* __restrict__ w_in,
                                               const float* __restrict__ b_in) {
    int b = blockIdx.x;
    int t = threadIdx.x;
    __shared__ float r_s[CH], sq_s[CH], alpha_s[CH], beta_s[CH];
    r_s[t]  = g_r[b][t];
    sq_s[t] = g_S[b][t][t];
    __syncthreads();
    int g0 = (t >> 4) << 4;
    float sum = 0.f, sumsq = 0.f;
    #pragma unroll
    for (int i = 0; i < GSIZE; ++i) { sum += r_s[g0 + i]; sumsq += sq_s[g0 + i]; }
    const float inv_cnt = 1.f / (float)(GSIZE * SP);
    float mu  = sum * inv_cnt;
    float var = sumsq * inv_cnt - mu * mu;
    float al = gn_w[t] * rsqrtf(var + EPS);
    float be = gn_b[t] - mu * al;
    alpha_s[t] = al; beta_s[t] = be;
    g_alpha[b][t] = al;
    __syncthreads();
    float bp = b_in[t], uu = 0.f;
    const float* wrow = w_in + t * CH;
    for (int c = 0; c < CH; ++c) {
        float w = wrow[c];
        bp += w * beta_s[c];
        uu += w * alpha_s[c] * r_s[c];
    }
    g_Bp[b][t] = bp;
    g_u[b][t]  = uu;
}

// ================= prep2: Gram -> softmax -> M (S read from L2) =================
__global__ __launch_bounds__(512) void k_prep2(const float* __restrict__ w_in,
                                               const float* __restrict__ w_out) {
    __shared__ float Whs[16][132], Ts[16][132];
    __shared__ float sc[16][17], Wt[16][17];

    int b = blockIdx.x >> 3, h = blockIdx.x & 7;
    int t = threadIdx.x;

    for (int idx = t; idx < 16 * CH; idx += 512) {
        int i = idx >> 7, k = idx & 127;
        Whs[i][k] = w_in[(h * 16 + i) * CH + k] * g_alpha[b][k];
    }
    __syncthreads();

    // T = Wh * S ; S row l straight from gmem (L2-hot), MLP via unroll
    {
        int l = t >> 2, ihb = (t & 3) * 4;
        const float4* Srow = (const float4*)&g_S[b][l][0];
        float ta[4] = {0.f, 0.f, 0.f, 0.f};
        #pragma unroll 4
        for (int k4 = 0; k4 < 32; ++k4) {
            float4 sv = __ldg(&Srow[k4]);
            #pragma unroll
            for (int i = 0; i < 4; ++i) {
                float4 wv = *(const float4*)&Whs[ihb + i][4 * k4];
                ta[i] += wv.x * sv.x + wv.y * sv.y + wv.z * sv.z + wv.w * sv.w;
            }
        }
        #pragma unroll
        for (int i = 0; i < 4; ++i) Ts[ihb + i][l] = ta[i];
    }
    __syncthreads();

    if (t < 256) {
        int i = t >> 4, j = t & 15;
        float g = 0.f;
        #pragma unroll 4
        for (int l4 = 0; l4 < 32; ++l4) {
            float4 tv = *(const float4*)&Ts[i][4 * l4];
            float4 wv = *(const float4*)&Whs[j][4 * l4];
            g += tv.x * wv.x + tv.y * wv.y + tv.z * wv.z + tv.w * wv.w;
        }
        float ui = g_u[b][h*16 + i], bi = g_Bp[b][h*16 + i];
        float uj = g_u[b][h*16 + j], bj = g_Bp[b][h*16 + j];
        sc[i][j] = 0.25f * (g + ui*bj + bi*uj + (float)SP * bi * bj);
    }
    __syncthreads();

    if (t < 16) {
        float m = sc[t][0];
        #pragma unroll
        for (int j = 1; j < 16; ++j) m = fmaxf(m, sc[t][j]);
        float e[16], s = 0.f;
        #pragma unroll
        for (int j = 0; j < 16; ++j) { e[j] = expf(sc[t][j] - m); s += e[j]; }
        float inv = 1.f / s;
        #pragma unroll
        for (int j = 0; j < 16; ++j) Wt[t][j] = e[j] * inv;
    }
    __syncthreads();

    {
        int o = t >> 2, jhb = (t & 3) * 4;
        float wo[16];
        #pragma unroll
        for (int i = 0; i < 16; ++i) wo[i] = w_out[o * CH + h * 16 + i];
        #pragma unroll
        for (int j = 0; j < 4; ++j) {
            float m = 0.f;
            #pragma unroll
            for (int i = 0; i < 16; ++i) m += wo[i] * Wt[i][jhb + j];
            g_M[b][o][h * 16 + jhb + j] = m;
        }
    }
}

// ===== prep3: A = (M W' + I) bf16 hi/lo [o][c]; d = M B' + b_out =====
__global__ __launch_bounds__(128) void k_prep3(const float* __restrict__ w_in,
                                               const float* __restrict__ b_out) {
    int b = blockIdx.y, o0 = blockIdx.x * 16;
    int t = threadIdx.x;  // = c
    __shared__ float Ms[16][CH];
    __shared__ float Bp_s[CH];
    for (int idx = t; idx < 16 * CH; idx += 128) {
        int i = idx >> 7, k = idx & 127;
        Ms[i][k] = g_M[b][o0 + i][k];
    }
    Bp_s[t] = g_Bp[b][t];
    __syncthreads();
    float a[16];
    #pragma unroll
    for (int i = 0; i < 16; ++i) a[i] = 0.f;
    for (int k = 0; k < CH; ++k) {
        float wv = w_in[k * CH + t];
        #pragma unroll
        for (int i = 0; i < 16; ++i) a[i] += Ms[i][k] * wv;
    }
    float al = g_alpha[b][t];
    #pragma unroll
    for (int i = 0; i < 16; ++i) {
        float v = al * a[i];
        if (o0 + i == t) v += 1.0f;
        __nv_bfloat16 hh = __float2bfloat16(v);
        g_Ahi[b][(o0 + i) * CH + t] = hh;
        g_Alo[b][(o0 + i) * CH + t] = __float2bfloat16(v - __bfloat162float(hh));
    }
    if (t < 16) {
        float dv = b_out[o0 + t];
        for (int k = 0; k < CH; ++k) dv += Ms[t][k] * Bp_s[k];
        g_d[b][o0 + t] = dv;
    }
}

// ================= main: out = (C+I) x + d via HMMA, cp.async pipelined =======
#define MA_AH  0                     // 128 x 272 B
#define MA_AL  34816
#define MA_XTH 69632                 // 64 x 272 B
#define MA_XTL 87040
#define MA_XS0 104448                // fp32 [128][68]
#define MA_XS1 139264
#define MA_DS  174080
#define MA_SMEM 174592
#define MA_NT 7
#define MA_BX 37
__global__ __launch_bounds__(256, 1) void k_main_mma2(const float* __restrict__ x,
                                                      float* __restrict__ out) {
    extern __shared__ __align__(16) char sm[];
    uint32_t sb = smem_u32(sm);
    int b = blockIdx.y, bx = blockIdx.x;
    int t = threadIdx.x;
    int wid = t >> 5, lane = t & 31, g = lane >> 2, tg = lane & 3;
    int m0 = (wid >> 1) * 32, n0 = (wid & 1) * 32;

    const float* xb = x + (size_t)b * BSTRIDE;
    float* ob = out + (size_t)b * BSTRIDE;
    const float* ds = (const float*)(sm + MA_DS);

    // prologue group: A hi/lo + d + tile0
    {
        const char* Ah = (const char*)&g_Ahi[b][0];
        const char* Al = (const char*)&g_Alo[b][0];
        #pragma unroll
        for (int w = 0; w < 8; ++w) {
            int m = t + 256*w;
            int o = m >> 4, cg = m & 15;
            uint32_t doff = (uint32_t)o*272 + cg*16;
            CP_ASYNC16(sb + MA_AH + doff, Ah + m*16);
            CP_ASYNC16(sb + MA_AL + doff, Al + m*16);
        }
        if (t < 32) CP_ASYNC16(sb + MA_DS + t*16, (const char*)&g_d[b][0] + t*16);
        int st0 = bx;   // bx < 37 < 256 always valid
        #pragma unroll
        for (int w = 0; w < 8; ++w) {
            int fidx = t + 256*w;
            int c = fidx >> 4, f4 = fidx & 15;
            CP_ASYNC16(sb + MA_XS0 + (uint32_t)(c*68 + 4*f4)*4,
                       xb + (size_t)c*SP + st0*64 + 4*f4);
        }
        CP_COMMIT();
    }

    for (int it = 0; it < MA_NT; ++it) {
        int st = bx + MA_BX*it;
        bool valid = st < 256;
        int buf = it & 1;
        if (it + 1 < MA_NT) {
            int stn = bx + MA_BX*(it+1);
            if (stn > 255) stn = 255;   // safe dummy load
            int nbuf = buf ^ 1;
            #pragma unroll
            for (int w = 0; w < 8; ++w) {
                int fidx = t + 256*w;
                int c = fidx >> 4, f4 = fidx & 15;
                CP_ASYNC16(sb + (nbuf ? MA_XS1 : MA_XS0) + (uint32_t)(c*68 + 4*f4)*4,
                           xb + (size_t)c*SP + stn*64 + 4*f4);
            }
            CP_COMMIT();
            CP_WAIT1();
        } else {
            CP_WAIT0();
        }
        __syncthreads();    // staged data visible; prev mma done reading XT

        // convert XS(buf) -> XT hi/lo ([s][c], padded 272B rows)
        const float* xsB = (const float*)(sm + (buf ? MA_XS1 : MA_XS0));
        #pragma unroll
        for (int w = 0; w < 8; ++w) {
            int u = t + 256*w;
            int s = u & 63, c4 = u >> 6;            // c4: 0..31 (4-channel group)
            float f0 = xsB[(4*c4 + 0)*68 + s];
            float f1 = xsB[(4*c4 + 1)*68 + s];
            float f2 = xsB[(4*c4 + 2)*68 + s];
            float f3 = xsB[(4*c4 + 3)*68 + s];
            uint32_t h01, l01, h23, l23;
            split2(f0, f1, h01, l01);
            split2(f2, f3, h23, l23);
            uint32_t off = (uint32_t)s*272 + c4*8;
            *(uint32_t*)(sm + MA_XTH + off)     = h01;
            *(uint32_t*)(sm + MA_XTH + off + 4) = h23;
            *(uint32_t*)(sm + MA_XTL + off)     = l01;
            *(uint32_t*)(sm + MA_XTL + off + 4) = l23;
        }
        __syncthreads();

        float acc[2][4][4];
        #pragma unroll
        for (int i = 0; i < 2; ++i)
            #pragma unroll
            for (int j = 0; j < 4; ++j)
                #pragma unroll
                for (int q = 0; q < 4; ++q) acc[i][j][q] = 0.f;

        #pragma unroll
        for (int k = 0; k < 8; ++k) {
            uint32_t koff = (uint32_t)k*32 + tg*4;
            uint32_t ah[2][4], al[2][4];
            #pragma unroll
            for (int i = 0; i < 2; ++i) {
                uint32_t r0 = (uint32_t)(m0 + 16*i + g)*272 + koff;
                uint32_t r1 = r0 + 8*272;
                ah[i][0] = *(const uint32_t*)(sm + MA_AH + r0);
                ah[i][1] = *(const uint32_t*)(sm + MA_AH + r1);
                ah[i][2] = *(const uint32_t*)(sm + MA_AH + r0 + 16);
                ah[i][3] = *(const uint32_t*)(sm + MA_AH + r1 + 16);
                al[i][0] = *(const uint32_t*)(sm + MA_AL + r0);
                al[i][1] = *(const uint32_t*)(sm + MA_AL + r1);
                al[i][2] = *(const uint32_t*)(sm + MA_AL + r0 + 16);
                al[i][3] = *(const uint32_t*)(sm + MA_AL + r1 + 16);
            }
            #pragma unroll
            for (int j = 0; j < 4; ++j) {
                uint32_t rb = (uint32_t)(n0 + 8*j + g)*272 + koff;
                uint32_t bh0 = *(const uint32_t*)(sm + MA_XTH + rb);
                uint32_t bh1 = *(const uint32_t*)(sm + MA_XTH + rb + 16);
                uint32_t bl0 = *(const uint32_t*)(sm + MA_XTL + rb);
                uint32_t bl1 = *(const uint32_t*)(sm + MA_XTL + rb + 16);
                #pragma unroll
                for (int i = 0; i < 2; ++i) {
                    mma16816(acc[i][j], ah[i][0], ah[i][1], ah[i][2], ah[i][3], bh0, bh1);
                    mma16816(acc[i][j], ah[i][0], ah[i][1], ah[i][2], ah[i][3], bl0, bl1);
                    mma16816(acc[i][j], al[i][0], al[i][1], al[i][2], al[i][3], bh0, bh1);
                }
            }
        }

        if (valid) {
            int s0 = st * 64;
            #pragma unroll
            for (int i = 0; i < 2; ++i) {
                int r0 = m0 + 16*i + g, r1 = r0 + 8;
                float d0 = ds[r0], d1 = ds[r1];
                #pragma unroll
                for (int j = 0; j < 4; ++j) {
                    int scol = s0 + n0 + 8*j + 2*tg;
                    float2 v0 = { acc[i][j][0] + d0, acc[i][j][1] + d0 };
                    float2 v1 = { acc[i][j][2] + d1, acc[i][j][3] + d1 };
                    *(float2*)(ob + (size_t)r0 * SP + scol) = v0;
                    *(float2*)(ob + (size_t)r1 * SP + scol) = v1;
                }
            }
        }
    }
}

extern "C" void kernel_launch(void* const* d_in, const int* in_sizes, int n_in,
                              void* d_out, int out_size) {
    const float* x    = (const float*)d_in[0];
    const float* gn_w = (const float*)d_in[1];
    const float* gn_b = (const float*)d_in[2];
    const float* w_in = (const float*)d_in[3];
    const float* b_in = (const float*)d_in[4];
    const float* w_out= (const float*)d_in[5];
    const float* b_out= (const float*)d_in[6];
    float* out = (float*)d_out;
    (void)in_sizes; (void)n_in; (void)out_size;

    cudaFuncSetAttribute(k_syrk_mma,  cudaFuncAttributeMaxDynamicSharedMemorySize, SK_SMEM);
    cudaFuncSetAttribute(k_main_mma2, cudaFuncAttributeMaxDynamicSharedMemorySize, MA_SMEM);

    k_zero<<<512, 256>>>();
    k_syrk_mma<<<dim3(32, NB), 256, SK_SMEM>>>(x);
    k_prep1<<<NB, 128>>>(gn_w, gn_b, w_in, b_in);
    k_prep2<<<64, 512>>>(w_in, w_out);
    k_prep3<<<dim3(8, NB), 128>>>(w_in, b_out);
    k_main_mma2<<<dim3(MA_BX, NB), 256, MA_SMEM>>>(x, out);
}

// round 9
// speedup vs baseline: 1.5560x; 1.0733x over previous
#include <cuda_runtime.h>
#include <cuda_bf16.h>
#include <cstdint>

#define CH 128
#define NB 8
#define SP 16384              // spatial = 128*128
#define BSTRIDE (CH*SP)
#define GSIZE 16
#define EPS 1e-5f

// ---------------- helpers ----------------
__device__ __forceinline__ uint32_t smem_u32(const void* p) {
    uint32_t a;
    asm("{ .reg .u64 t; cvta.to.shared.u64 t, %1; cvt.u32.u64 %0, t; }" : "=r"(a) : "l"(p));
    return a;
}
#define CP_ASYNC16(dst, src) \
    asm volatile("cp.async.cg.shared.global [%0], [%1], 16;" :: "r"(dst), "l"(src) : "memory")
#define CP_COMMIT() asm volatile("cp.async.commit_group;" ::: "memory")
#define CP_WAIT1()  asm volatile("cp.async.wait_group 1;" ::: "memory")
#define CP_WAIT0()  asm volatile("cp.async.wait_group 0;" ::: "memory")

__device__ __forceinline__ void mma16816(float* c, uint32_t a0, uint32_t a1,
                                         uint32_t a2, uint32_t a3,
                                         uint32_t b0, uint32_t b1) {
    asm volatile("mma.sync.aligned.m16n8k16.row.col.f32.bf16.bf16.f32 "
                 "{%0,%1,%2,%3}, {%4,%5,%6,%7}, {%8,%9}, {%0,%1,%2,%3};"
                 : "+f"(c[0]), "+f"(c[1]), "+f"(c[2]), "+f"(c[3])
                 : "r"(a0), "r"(a1), "r"(a2), "r"(a3), "r"(b0), "r"(b1));
}

// fast packed split: 4 fp32 -> bf16x2 hi words + bf16x2 lo words (pairs (x,y),(z,w))
__device__ __forceinline__ void split4(float4 v, uint32_t& h01, uint32_t& h23,
                                       uint32_t& l01, uint32_t& l23) {
    asm("cvt.rn.bf16x2.f32 %0, %1, %2;" : "=r"(h01) : "f"(v.y), "f"(v.x));
    asm("cvt.rn.bf16x2.f32 %0, %1, %2;" : "=r"(h23) : "f"(v.w), "f"(v.z));
    float hx = __uint_as_float(h01 << 16);
    float hy = __uint_as_float(h01 & 0xFFFF0000u);
    float hz = __uint_as_float(h23 << 16);
    float hw = __uint_as_float(h23 & 0xFFFF0000u);
    float lx = v.x - hx, ly = v.y - hy, lz = v.z - hz, lw = v.w - hw;
    asm("cvt.rn.bf16x2.f32 %0, %1, %2;" : "=r"(l01) : "f"(ly), "f"(lx));
    asm("cvt.rn.bf16x2.f32 %0, %1, %2;" : "=r"(l23) : "f"(lw), "f"(lz));
}

// ---------------- device scratch ----------------
__device__ float g_S[NB][CH][CH];
__device__ float g_r[NB][CH];
__device__ float g_alpha[NB][CH];
__device__ float g_Bp[NB][CH];
__device__ float g_u[NB][CH];
__device__ float g_M[NB][CH][CH];
__device__ __align__(16) __nv_bfloat16 g_Ahi[NB][CH*CH];  // (C+I)[o][c] hi
__device__ __align__(16) __nv_bfloat16 g_Alo[NB][CH*CH];  // (C+I)[o][c] lo
__device__ __align__(16) float g_d[NB][CH];

__global__ void k_zero() {
    int idx = blockIdx.x * blockDim.x + threadIdx.x;
    if (idx < NB*CH*CH) ((float*)g_S)[idx] = 0.f;
    if (idx < NB*CH)    ((float*)g_r)[idx] = 0.f;
}

// ================= syrk via HMMA: S = X X^T (full), + row sums =================
#define SK_XH  0                         // 128 rows x 144 B (64 bf16 + pad)
#define SK_XL  18432
#define SK_XS0 36864                     // fp32 staging [128][68]
#define SK_XS1 71680
#define SK_SMEM 106496
__global__ __launch_bounds__(256, 2) void k_syrk_mma(const float* __restrict__ x) {
    extern __shared__ __align__(16) char sm[];
    uint32_t sb = smem_u32(sm);
    int b = blockIdx.y;
    int chunk0 = blockIdx.x * 512;
    int t = threadIdx.x;
    int wid = t >> 5, lane = t & 31, g = lane >> 2, tg = lane & 3;
    int m0 = (wid >> 1) * 32, n0 = (wid & 1) * 64;

    const float* xb = x + (size_t)b * BSTRIDE + chunk0;

    #pragma unroll
    for (int w = 0; w < 8; ++w) {
        int fidx = t + 256*w;
        int c = fidx >> 4, f4 = fidx & 15;
        CP_ASYNC16(sb + SK_XS0 + (uint32_t)(c*68 + 4*f4)*4,
                   xb + (size_t)c*SP + 4*f4);
    }
    CP_COMMIT();

    float acc[2][8][4];
    #pragma unroll
    for (int i = 0; i < 2; ++i)
        #pragma unroll
        for (int j = 0; j < 8; ++j)
            #pragma unroll
            for (int q = 0; q < 4; ++q) acc[i][j][q] = 0.f;
    float rs[8];
    #pragma unroll
    for (int w = 0; w < 8; ++w) rs[w] = 0.f;

    for (int tile = 0; tile < 8; ++tile) {
        int buf = tile & 1;
        if (tile + 1 < 8) {
            int nbuf = buf ^ 1;
            #pragma unroll
            for (int w = 0; w < 8; ++w) {
                int fidx = t + 256*w;
                int c = fidx >> 4, f4 = fidx & 15;
                CP_ASYNC16(sb + (nbuf ? SK_XS1 : SK_XS0) + (uint32_t)(c*68 + 4*f4)*4,
                           xb + (size_t)c*SP + (tile+1)*64 + 4*f4);
            }
            CP_COMMIT();
            CP_WAIT1();
        } else {
            CP_WAIT0();
        }
        __syncthreads();

        const float* xsB = (const float*)(sm + (buf ? SK_XS1 : SK_XS0));
        #pragma unroll
        for (int w = 0; w < 8; ++w) {
            int fidx = t + 256*w;
            int c = fidx >> 4, f4 = fidx & 15;
            float4 v = *(const float4*)(xsB + c*68 + 4*f4);
            rs[w] += v.x + v.y + v.z + v.w;
            uint32_t h01, h23, l01, l23;
            split4(v, h01, h23, l01, l23);
            uint32_t off = (uint32_t)c*144 + f4*8;
            *(uint2*)(sm + SK_XH + off) = make_uint2(h01, h23);
            *(uint2*)(sm + SK_XL + off) = make_uint2(l01, l23);
        }
        __syncthreads();

        #pragma unroll
        for (int k = 0; k < 4; ++k) {
            uint32_t koff = (uint32_t)k*32 + tg*4;
            uint32_t ah[2][4], al[2][4];
            #pragma unroll
            for (int i = 0; i < 2; ++i) {
                uint32_t r0 = (uint32_t)(m0 + 16*i + g)*144 + koff;
                uint32_t r1 = r0 + 8*144;
                ah[i][0] = *(const uint32_t*)(sm + SK_XH + r0);
                ah[i][1] = *(const uint32_t*)(sm + SK_XH + r1);
                ah[i][2] = *(const uint32_t*)(sm + SK_XH + r0 + 16);
                ah[i][3] = *(const uint32_t*)(sm + SK_XH + r1 + 16);
                al[i][0] = *(const uint32_t*)(sm + SK_XL + r0);
                al[i][1] = *(const uint32_t*)(sm + SK_XL + r1);
                al[i][2] = *(const uint32_t*)(sm + SK_XL + r0 + 16);
                al[i][3] = *(const uint32_t*)(sm + SK_XL + r1 + 16);
            }
            #pragma unroll
            for (int j = 0; j < 8; ++j) {
                uint32_t rb = (uint32_t)(n0 + 8*j + g)*144 + koff;
                uint32_t bh0 = *(const uint32_t*)(sm + SK_XH + rb);
                uint32_t bh1 = *(const uint32_t*)(sm + SK_XH + rb + 16);
                uint32_t bl0 = *(const uint32_t*)(sm + SK_XL + rb);
                uint32_t bl1 = *(const uint32_t*)(sm + SK_XL + rb + 16);
                #pragma unroll
                for (int i = 0; i < 2; ++i) {
                    mma16816(acc[i][j], ah[i][0], ah[i][1], ah[i][2], ah[i][3], bh0, bh1);
                    mma16816(acc[i][j], ah[i][0], ah[i][1], ah[i][2], ah[i][3], bl0, bl1);
                    mma16816(acc[i][j], al[i][0], al[i][1], al[i][2], al[i][3], bh0, bh1);
                }
            }
        }
    }

    #pragma unroll
    for (int i = 0; i < 2; ++i)
        #pragma unroll
        for (int j = 0; j < 8; ++j) {
            int r0 = m0 + 16*i + g, r1 = r0 + 8;
            int col = n0 + 8*j + 2*tg;
            atomicAdd(&g_S[b][r0][col],     acc[i][j][0]);
            atomicAdd(&g_S[b][r0][col + 1], acc[i][j][1]);
            atomicAdd(&g_S[b][r1][col],     acc[i][j][2]);
            atomicAdd(&g_S[b][r1][col + 1], acc[i][j][3]);
        }
    #pragma unroll
    for (int w = 0; w < 8; ++w)
        atomicAdd(&g_r[b][(t >> 4) + 16*w], rs[w]);
}

// ================= prep1: GN stats, alpha/beta, B', u (512 thr) =================
__global__ __launch_bounds__(512) void k_prep1(const float* __restrict__ gn_w,
                                               const float* __restrict__ gn_b,
                                               const float* __restrict__ w_in,
                                               const float* __restrict__ b_in) {
    int b = blockIdx.x;
    int t = threadIdx.x;
    __shared__ float r_s[CH], alpha_s[CH], beta_s[CH];
    if (t < CH) {
        float rv = g_r[b][t];
        float sq = g_S[b][t][t];
        r_s[t] = rv;
        // group stats via smem after sync (need whole group) — store sq temporarily
        alpha_s[t] = sq;   // temp: sumsq holder
    }
    __syncthreads();
    if (t < CH) {
        int g0 = (t >> 4) << 4;
        float sum = 0.f, sumsq = 0.f;
        #pragma unroll
        for (int i = 0; i < GSIZE; ++i) { sum += r_s[g0 + i]; sumsq += alpha_s[g0 + i]; }
        const float inv_cnt = 1.f / (float)(GSIZE * SP);
        float mu  = sum * inv_cnt;
        float var = sumsq * inv_cnt - mu * mu;
        float al = gn_w[t] * rsqrtf(var + EPS);
        beta_s[t] = gn_b[t] - mu * al;
        g_alpha[b][t] = al;
    }
    __syncthreads();
    if (t < CH) alpha_s[t] = g_alpha[b][t];
    __syncthreads();
    // B'[o], u[o]: o = t>>2, lane-quarter q sums 32 c's, shfl-reduce
    {
        int o = t >> 2, q = t & 3;
        const float* wrow = w_in + o * CH + q * 32;
        float bp = 0.f, uu = 0.f;
        #pragma unroll 8
        for (int c = 0; c < 32; ++c) {
            float w = wrow[c];
            int cc = q * 32 + c;
            bp += w * beta_s[cc];
            uu += w * alpha_s[cc] * r_s[cc];
        }
        bp += __shfl_xor_sync(0xFFFFFFFF, bp, 1);
        uu += __shfl_xor_sync(0xFFFFFFFF, uu, 1);
        bp += __shfl_xor_sync(0xFFFFFFFF, bp, 2);
        uu += __shfl_xor_sync(0xFFFFFFFF, uu, 2);
        if (q == 0) {
            g_Bp[b][o] = bp + b_in[o];
            g_u[b][o]  = uu;
        }
    }
}

// ================= prep2: Gram -> softmax -> M (1024 thr, S staged) ============
#define P2_SF   (128*132)
#define P2_WF   (16*132)
#define P2_SMEM ((P2_SF + 2*P2_WF + 2*16*17) * 4)
__global__ __launch_bounds__(1024) void k_prep2(const float* __restrict__ w_in,
                                                const float* __restrict__ w_out) {
    extern __shared__ float sm2[];
    float* Ss  = sm2;                    // [128][132]
    float* Whs = Ss + P2_SF;             // [16][132]
    float* Ts  = Whs + P2_WF;            // [16][132]
    float* sc  = Ts + P2_WF;             // [16][17]
    float* Wt  = sc + 16*17;             // [16][17]
    uint32_t sb = smem_u32(sm2);

    int b = blockIdx.x >> 3, h = blockIdx.x & 7;
    int t = threadIdx.x;

    // stage S via cp.async (rows padded to 132)
    #pragma unroll
    for (int w = 0; w < 4; ++w) {
        int m = t + 1024*w;              // 4096 chunks of 16B
        int row = m >> 5, c16 = m & 31;
        CP_ASYNC16(sb + (uint32_t)(row*132 + 4*c16)*4, &g_S[b][row][4*c16]);
    }
    CP_COMMIT();
    // Wh scaled (overlaps cp.async)
    for (int idx = t; idx < 16 * CH; idx += 1024) {
        int i = idx >> 7, k = idx & 127;
        Whs[i*132 + k] = w_in[(h*16 + i)*CH + k] * g_alpha[b][k];
    }
    CP_WAIT0();
    __syncthreads();

    // T[i][l] = sum_c Whs[i][c] * S[l][c]  (symmetry);  l = t>>3, i = t&7 and +8
    {
        int l = t >> 3, i0 = t & 7;
        float ta0 = 0.f, ta1 = 0.f;
        #pragma unroll 4
        for (int k4 = 0; k4 < 32; ++k4) {
            float4 sv = *(const float4*)&Ss[l*132 + 4*k4];
            float4 w0 = *(const float4*)&Whs[i0*132 + 4*k4];
            float4 w1 = *(const float4*)&Whs[(i0 + 8)*132 + 4*k4];
            ta0 += w0.x*sv.x + w0.y*sv.y + w0.z*sv.z + w0.w*sv.w;
            ta1 += w1.x*sv.x + w1.y*sv.y + w1.z*sv.z + w1.w*sv.w;
        }
        Ts[i0*132 + l]       = ta0;
        Ts[(i0 + 8)*132 + l] = ta1;
    }
    __syncthreads();

    if (t < 256) {
        int i = t >> 4, j = t & 15;
        float g = 0.f;
        #pragma unroll 4
        for (int l4 = 0; l4 < 32; ++l4) {
            float4 tv = *(const float4*)&Ts[i*132 + 4*l4];
            float4 wv = *(const float4*)&Whs[j*132 + 4*l4];
            g += tv.x*wv.x + tv.y*wv.y + tv.z*wv.z + tv.w*wv.w;
        }
        float ui = g_u[b][h*16 + i], bi = g_Bp[b][h*16 + i];
        float uj = g_u[b][h*16 + j], bj = g_Bp[b][h*16 + j];
        sc[i*17 + j] = 0.25f * (g + ui*bj + bi*uj + (float)SP * bi * bj);
    }
    __syncthreads();

    if (t < 16) {
        float m = sc[t*17 + 0];
        #pragma unroll
        for (int j = 1; j < 16; ++j) m = fmaxf(m, sc[t*17 + j]);
        float e[16], s = 0.f;
        #pragma unroll
        for (int j = 0; j < 16; ++j) { e[j] = expf(sc[t*17 + j] - m); s += e[j]; }
        float inv = 1.f / s;
        #pragma unroll
        for (int j = 0; j < 16; ++j) Wt[t*17 + j] = e[j] * inv;
    }
    __syncthreads();

    // M[o][h*16+j]: o = t>>3, j = 2*(t&7), +1
    {
        int o = t >> 3, j0 = (t & 7) * 2;
        float m0 = 0.f, m1 = 0.f;
        const float* wrow = w_out + o*CH + h*16;
        #pragma unroll
        for (int i = 0; i < 16; ++i) {
            float wo = wrow[i];
            m0 += wo * Wt[i*17 + j0];
            m1 += wo * Wt[i*17 + j0 + 1];
        }
        g_M[b][o][h*16 + j0]     = m0;
        g_M[b][o][h*16 + j0 + 1] = m1;
    }
}

// ===== prep3: A = (M W' + I) bf16 hi/lo [o][c]; d = M B' + b_out (8 rows/blk) ==
__global__ __launch_bounds__(128) void k_prep3(const float* __restrict__ w_in,
                                               const float* __restrict__ b_out) {
    int b = blockIdx.y, o0 = blockIdx.x * 8;
    int t = threadIdx.x;  // = c
    __shared__ float Ms[8][CH];
    __shared__ float Bp_s[CH];
    for (int idx = t; idx < 8 * CH; idx += 128) {
        int i = idx >> 7, k = idx & 127;
        Ms[i][k] = g_M[b][o0 + i][k];
    }
    Bp_s[t] = g_Bp[b][t];
    __syncthreads();
    float a[8];
    #pragma unroll
    for (int i = 0; i < 8; ++i) a[i] = 0.f;
    for (int k = 0; k < CH; ++k) {
        float wv = w_in[k * CH + t];
        #pragma unroll
        for (int i = 0; i < 8; ++i) a[i] += Ms[i][k] * wv;
    }
    float al = g_alpha[b][t];
    #pragma unroll
    for (int i = 0; i < 8; ++i) {
        float v = al * a[i];
        if (o0 + i == t) v += 1.0f;
        __nv_bfloat16 hh = __float2bfloat16(v);
        g_Ahi[b][(o0 + i) * CH + t] = hh;
        g_Alo[b][(o0 + i) * CH + t] = __float2bfloat16(v - __bfloat162float(hh));
    }
    if (t < 8) {
        float dv = b_out[o0 + t];
        for (int k = 0; k < CH; ++k) dv += Ms[t][k] * Bp_s[k];
        g_d[b][o0 + t] = dv;
    }
}

// ================= main: out = (C+I) x + d via HMMA, cp.async pipelined =======
#define MA_AH  0                     // 128 x 272 B
#define MA_AL  34816
#define MA_XTH 69632                 // 64 x 272 B
#define MA_XTL 87040
#define MA_XS0 104448                // fp32 [128][68]
#define MA_XS1 139264
#define MA_DS  174080
#define MA_SMEM 174592
#define MA_NT 7
#define MA_BX 37
__global__ __launch_bounds__(256, 1) void k_main_mma2(const float* __restrict__ x,
                                                      float* __restrict__ out) {
    extern __shared__ __align__(16) char sm[];
    uint32_t sb = smem_u32(sm);
    int b = blockIdx.y, bx = blockIdx.x;
    int t = threadIdx.x;
    int wid = t >> 5, lane = t & 31, g = lane >> 2, tg = lane & 3;
    int m0 = (wid >> 1) * 32, n0 = (wid & 1) * 32;

    const float* xb = x + (size_t)b * BSTRIDE;
    float* ob = out + (size_t)b * BSTRIDE;
    const float* ds = (const float*)(sm + MA_DS);

    {
        const char* Ah = (const char*)&g_Ahi[b][0];
        const char* Al = (const char*)&g_Alo[b][0];
        #pragma unroll
        for (int w = 0; w < 8; ++w) {
            int m = t + 256*w;
            int o = m >> 4, cg = m & 15;
            uint32_t doff = (uint32_t)o*272 + cg*16;
            CP_ASYNC16(sb + MA_AH + doff, Ah + m*16);
            CP_ASYNC16(sb + MA_AL + doff, Al + m*16);
        }
        if (t < 32) CP_ASYNC16(sb + MA_DS + t*16, (const char*)&g_d[b][0] + t*16);
        int st0 = bx;
        #pragma unroll
        for (int w = 0; w < 8; ++w) {
            int fidx = t + 256*w;
            int c = fidx >> 4, f4 = fidx & 15;
            CP_ASYNC16(sb + MA_XS0 + (uint32_t)(c*68 + 4*f4)*4,
                       xb + (size_t)c*SP + st0*64 + 4*f4);
        }
        CP_COMMIT();
    }

    for (int it = 0; it < MA_NT; ++it) {
        int st = bx + MA_BX*it;
        bool valid = st < 256;
        int buf = it & 1;
        if (it + 1 < MA_NT) {
            int stn = bx + MA_BX*(it+1);
            if (stn > 255) stn = 255;
            int nbuf = buf ^ 1;
            #pragma unroll
            for (int w = 0; w < 8; ++w) {
                int fidx = t + 256*w;
                int c = fidx >> 4, f4 = fidx & 15;
                CP_ASYNC16(sb + (nbuf ? MA_XS1 : MA_XS0) + (uint32_t)(c*68 + 4*f4)*4,
                           xb + (size_t)c*SP + stn*64 + 4*f4);
            }
            CP_COMMIT();
            CP_WAIT1();
        } else {
            CP_WAIT0();
        }
        __syncthreads();

        const float* xsB = (const float*)(sm + (buf ? MA_XS1 : MA_XS0));
        #pragma unroll
        for (int w = 0; w < 8; ++w) {
            int u = t + 256*w;
            int s = u & 63, c4 = u >> 6;
            float4 v;
            v.x = xsB[(4*c4 + 0)*68 + s];
            v.y = xsB[(4*c4 + 1)*68 + s];
            v.z = xsB[(4*c4 + 2)*68 + s];
            v.w = xsB[(4*c4 + 3)*68 + s];
            uint32_t h01, h23, l01, l23;
            split4(v, h01, h23, l01, l23);
            uint32_t off = (uint32_t)s*272 + c4*8;
            *(uint2*)(sm + MA_XTH + off) = make_uint2(h01, h23);
            *(uint2*)(sm + MA_XTL + off) = make_uint2(l01, l23);
        }
        __syncthreads();

        float acc[2][4][4];
        #pragma unroll
        for (int i = 0; i < 2; ++i)
            #pragma unroll
            for (int j = 0; j < 4; ++j)
                #pragma unroll
                for (int q = 0; q < 4; ++q) acc[i][j][q] = 0.f;

        #pragma unroll
        for (int k = 0; k < 8; ++k) {
            uint32_t koff = (uint32_t)k*32 + tg*4;
            uint32_t ah[2][4], al[2][4];
            #pragma unroll
            for (int i = 0; i < 2; ++i) {
                uint32_t r0 = (uint32_t)(m0 + 16*i + g)*272 + koff;
                uint32_t r1 = r0 + 8*272;
                ah[i][0] = *(const uint32_t*)(sm + MA_AH + r0);
                ah[i][1] = *(const uint32_t*)(sm + MA_AH + r1);
                ah[i][2] = *(const uint32_t*)(sm + MA_AH + r0 + 16);
                ah[i][3] = *(const uint32_t*)(sm + MA_AH + r1 + 16);
                al[i][0] = *(const uint32_t*)(sm + MA_AL + r0);
                al[i][1] = *(const uint32_t*)(sm + MA_AL + r1);
                al[i][2] = *(const uint32_t*)(sm + MA_AL + r0 + 16);
                al[i][3] = *(const uint32_t*)(sm + MA_AL + r1 + 16);
            }
            #pragma unroll
            for (int j = 0; j < 4; ++j) {
                uint32_t rb = (uint32_t)(n0 + 8*j + g)*272 + koff;
                uint32_t bh0 = *(const uint32_t*)(sm + MA_XTH + rb);
                uint32_t bh1 = *(const uint32_t*)(sm + MA_XTH + rb + 16);
                uint32_t bl0 = *(const uint32_t*)(sm + MA_XTL + rb);
                uint32_t bl1 = *(const uint32_t*)(sm + MA_XTL + rb + 16);
                #pragma unroll
                for (int i = 0; i < 2; ++i) {
                    mma16816(acc[i][j], ah[i][0], ah[i][1], ah[i][2], ah[i][3], bh0, bh1);
                    mma16816(acc[i][j], ah[i][0], ah[i][1], ah[i][2], ah[i][3], bl0, bl1);
                    mma16816(acc[i][j], al[i][0], al[i][1], al[i][2], al[i][3], bh0, bh1);
                }
            }
        }

        if (valid) {
            int s0 = st * 64;
            #pragma unroll
            for (int i = 0; i < 2; ++i) {
                int r0 = m0 + 16*i + g, r1 = r0 + 8;
                float d0 = ds[r0], d1 = ds[r1];
                #pragma unroll
                for (int j = 0; j < 4; ++j) {
                    int scol = s0 + n0 + 8*j + 2*tg;
                    float2 v0 = { acc[i][j][0] + d0, acc[i][j][1] + d0 };
                    float2 v1 = { acc[i][j][2] + d1, acc[i][j][3] + d1 };
                    *(float2*)(ob + (size_t)r0 * SP + scol) = v0;
                    *(float2*)(ob + (size_t)r1 * SP + scol) = v1;
                }
            }
        }
    }
}

extern "C" void kernel_launch(void* const* d_in, const int* in_sizes, int n_in,
                              void* d_out, int out_size) {
    const float* x    = (const float*)d_in[0];
    const float* gn_w = (const float*)d_in[1];
    const float* gn_b = (const float*)d_in[2];
    const float* w_in = (const float*)d_in[3];
    const float* b_in = (const float*)d_in[4];
    const float* w_out= (const float*)d_in[5];
    const float* b_out= (const float*)d_in[6];
    float* out = (float*)d_out;
    (void)in_sizes; (void)n_in; (void)out_size;

    cudaFuncSetAttribute(k_syrk_mma,  cudaFuncAttributeMaxDynamicSharedMemorySize, SK_SMEM);
    cudaFuncSetAttribute(k_prep2,     cudaFuncAttributeMaxDynamicSharedMemorySize, P2_SMEM);
    cudaFuncSetAttribute(k_main_mma2, cudaFuncAttributeMaxDynamicSharedMemorySize, MA_SMEM);

    k_zero<<<512, 256>>>();
    k_syrk_mma<<<dim3(32, NB), 256, SK_SMEM>>>(x);
    k_prep1<<<NB, 512>>>(gn_w, gn_b, w_in, b_in);
    k_prep2<<<64, 1024, P2_SMEM>>>(w_in, w_out);
    k_prep3<<<dim3(16, NB), 128>>>(w_in, b_out);
    k_main_mma2<<<dim3(MA_BX, NB), 256, MA_SMEM>>>(x, out);
}

// round 12
// speedup vs baseline: 1.5737x; 1.0113x over previous
#include <cuda_runtime.h>
#include <cuda_bf16.h>
#include <cstdint>

#define CH 128
#define NB 8
#define SP 16384              // spatial = 128*128
#define BSTRIDE (CH*SP)
#define GSIZE 16
#define EPS 1e-5f

// ---------------- helpers ----------------
__device__ __forceinline__ uint32_t smem_u32(const void* p) {
    uint32_t a;
    asm("{ .reg .u64 t; cvta.to.shared.u64 t, %1; cvt.u32.u64 %0, t; }" : "=r"(a) : "l"(p));
    return a;
}
#define CP_ASYNC16(dst, src) \
    asm volatile("cp.async.cg.shared.global [%0], [%1], 16;" :: "r"(dst), "l"(src) : "memory")
#define CP_COMMIT() asm volatile("cp.async.commit_group;" ::: "memory")
#define CP_WAIT1()  asm volatile("cp.async.wait_group 1;" ::: "memory")
#define CP_WAIT0()  asm volatile("cp.async.wait_group 0;" ::: "memory")

__device__ __forceinline__ void mma16816(float* c, uint32_t a0, uint32_t a1,
                                         uint32_t a2, uint32_t a3,
                                         uint32_t b0, uint32_t b1) {
    asm volatile("mma.sync.aligned.m16n8k16.row.col.f32.bf16.bf16.f32 "
                 "{%0,%1,%2,%3}, {%4,%5,%6,%7}, {%8,%9}, {%0,%1,%2,%3};"
                 : "+f"(c[0]), "+f"(c[1]), "+f"(c[2]), "+f"(c[3])
                 : "r"(a0), "r"(a1), "r"(a2), "r"(a3), "r"(b0), "r"(b1));
}
__device__ __forceinline__ void ldmx4(uint32_t* r, uint32_t addr) {
    asm volatile("ldmatrix.sync.aligned.m8n8.x4.shared.b16 {%0,%1,%2,%3}, [%4];"
                 : "=r"(r[0]), "=r"(r[1]), "=r"(r[2]), "=r"(r[3]) : "r"(addr));
}
__device__ __forceinline__ void ldmx2(uint32_t* r, uint32_t addr) {
    asm volatile("ldmatrix.sync.aligned.m8n8.x2.shared.b16 {%0,%1}, [%2];"
                 : "=r"(r[0]), "=r"(r[1]) : "r"(addr));
}

// fast packed split: 4 fp32 -> bf16x2 hi + lo words (pairs (x,y),(z,w))
__device__ __forceinline__ void split4(float4 v, uint32_t& h01, uint32_t& h23,
                                       uint32_t& l01, uint32_t& l23) {
    asm("cvt.rn.bf16x2.f32 %0, %1, %2;" : "=r"(h01) : "f"(v.y), "f"(v.x));
    asm("cvt.rn.bf16x2.f32 %0, %1, %2;" : "=r"(h23) : "f"(v.w), "f"(v.z));
    float hx = __uint_as_float(h01 << 16);
    float hy = __uint_as_float(h01 & 0xFFFF0000u);
    float hz = __uint_as_float(h23 << 16);
    float hw = __uint_as_float(h23 & 0xFFFF0000u);
    float lx = v.x - hx, ly = v.y - hy, lz = v.z - hz, lw = v.w - hw;
    asm("cvt.rn.bf16x2.f32 %0, %1, %2;" : "=r"(l01) : "f"(ly), "f"(lx));
    asm("cvt.rn.bf16x2.f32 %0, %1, %2;" : "=r"(l23) : "f"(lw), "f"(lz));
}

// ---------------- device scratch ----------------
__device__ float g_S[NB][CH][CH];
__device__ float g_r[NB][CH];
__device__ float g_alpha[NB][CH];
__device__ float g_Bp[NB][CH];
__device__ float g_u[NB][CH];
__device__ float g_M[NB][CH][CH];
__device__ __align__(16) __nv_bfloat16 g_Ahi[NB][CH*CH];  // (C+I)[o][c] hi
__device__ __align__(16) __nv_bfloat16 g_Alo[NB][CH*CH];  // (C+I)[o][c] lo
__device__ __align__(16) float g_d[NB][CH];

__global__ void k_zero() {
    int idx = blockIdx.x * blockDim.x + threadIdx.x;
    if (idx < NB*CH*CH) ((float*)g_S)[idx] = 0.f;
    if (idx < NB*CH)    ((float*)g_r)[idx] = 0.f;
}

// ================= syrk via HMMA: S = X X^T (full), + row sums =================
#define SK_XH  0                         // 128 rows x 144 B (64 bf16 + pad)
#define SK_XL  18432
#define SK_XS0 36864                     // fp32 staging [128][68]
#define SK_XS1 71680
#define SK_SMEM 106496
__global__ __launch_bounds__(256, 2) void k_syrk_mma(const float* __restrict__ x) {
    extern __shared__ __align__(16) char sm[];
    uint32_t sb = smem_u32(sm);
    int b = blockIdx.y;
    int chunk0 = blockIdx.x * 512;
    int t = threadIdx.x;
    int wid = t >> 5, lane = t & 31, g = lane >> 2, tg = lane & 3;
    int m0 = (wid >> 1) * 32, n0 = (wid & 1) * 64;

    // ldmatrix lane base addresses
    uint32_t aBase0 = (uint32_t)(m0 + (lane & 15)) * 144 + (lane >> 4) * 16;
    uint32_t aBase1 = aBase0 + 16 * 144;
    uint32_t bBase[8];
    #pragma unroll
    for (int j = 0; j < 8; ++j)
        bBase[j] = (uint32_t)(n0 + 8*j + (lane & 7)) * 144 + ((lane >> 3) & 1) * 16;

    const float* xb = x + (size_t)b * BSTRIDE + chunk0;

    #pragma unroll
    for (int w = 0; w < 8; ++w) {
        int fidx = t + 256*w;
        int c = fidx >> 4, f4 = fidx & 15;
        CP_ASYNC16(sb + SK_XS0 + (uint32_t)(c*68 + 4*f4)*4,
                   xb + (size_t)c*SP + 4*f4);
    }
    CP_COMMIT();

    float acc[2][8][4];
    #pragma unroll
    for (int i = 0; i < 2; ++i)
        #pragma unroll
        for (int j = 0; j < 8; ++j)
            #pragma unroll
            for (int q = 0; q < 4; ++q) acc[i][j][q] = 0.f;
    float rs[8];
    #pragma unroll
    for (int w = 0; w < 8; ++w) rs[w] = 0.f;

    for (int tile = 0; tile < 8; ++tile) {
        int buf = tile & 1;
        if (tile + 1 < 8) {
            int nbuf = buf ^ 1;
            #pragma unroll
            for (int w = 0; w < 8; ++w) {
                int fidx = t + 256*w;
                int c = fidx >> 4, f4 = fidx & 15;
                CP_ASYNC16(sb + (nbuf ? SK_XS1 : SK_XS0) + (uint32_t)(c*68 + 4*f4)*4,
                           xb + (size_t)c*SP + (tile+1)*64 + 4*f4);
            }
            CP_COMMIT();
            CP_WAIT1();
        } else {
            CP_WAIT0();
        }
        __syncthreads();

        const float* xsB = (const float*)(sm + (buf ? SK_XS1 : SK_XS0));
        #pragma unroll
        for (int w = 0; w < 8; ++w) {
            int fidx = t + 256*w;
            int c = fidx >> 4, f4 = fidx & 15;
            float4 v = *(const float4*)(xsB + c*68 + 4*f4);
            rs[w] += v.x + v.y + v.z + v.w;
            uint32_t h01, h23, l01, l23;
            split4(v, h01, h23, l01, l23);
            uint32_t off = (uint32_t)c*144 + f4*8;
            *(uint2*)(sm + SK_XH + off) = make_uint2(h01, h23);
            *(uint2*)(sm + SK_XL + off) = make_uint2(l01, l23);
        }
        __syncthreads();

        #pragma unroll
        for (int k = 0; k < 4; ++k) {
            uint32_t koff = k * 32;
            uint32_t ah[2][4], al[2][4];
            ldmx4(ah[0], sb + SK_XH + aBase0 + koff);
            ldmx4(ah[1], sb + SK_XH + aBase1 + koff);
            ldmx4(al[0], sb + SK_XL + aBase0 + koff);
            ldmx4(al[1], sb + SK_XL + aBase1 + koff);
            #pragma unroll
            for (int j = 0; j < 8; ++j) {
                uint32_t bh[2], bl[2];
                ldmx2(bh, sb + SK_XH + bBase[j] + koff);
                ldmx2(bl, sb + SK_XL + bBase[j] + koff);
                #pragma unroll
                for (int i = 0; i < 2; ++i) {
                    mma16816(acc[i][j], ah[i][0], ah[i][1], ah[i][2], ah[i][3], bh[0], bh[1]);
                    mma16816(acc[i][j], ah[i][0], ah[i][1], ah[i][2], ah[i][3], bl[0], bl[1]);
                    mma16816(acc[i][j], al[i][0], al[i][1], al[i][2], al[i][3], bh[0], bh[1]);
                }
            }
        }
    }

    #pragma unroll
    for (int i = 0; i < 2; ++i)
        #pragma unroll
        for (int j = 0; j < 8; ++j) {
            int r0 = m0 + 16*i + g, r1 = r0 + 8;
            int col = n0 + 8*j + 2*tg;
            atomicAdd(&g_S[b][r0][col],     acc[i][j][0]);
            atomicAdd(&g_S[b][r0][col + 1], acc[i][j][1]);
            atomicAdd(&g_S[b][r1][col],     acc[i][j][2]);
            atomicAdd(&g_S[b][r1][col + 1], acc[i][j][3]);
        }
    #pragma unroll
    for (int w = 0; w < 8; ++w)
        atomicAdd(&g_r[b][(t >> 4) + 16*w], rs[w]);
}

// ================= prep1: GN stats, alpha/beta, B', u (512 thr) =================
__global__ __launch_bounds__(512) void k_prep1(const float* __restrict__ gn_w,
                                               const float* __restrict__ gn_b,
                                               const float* __restrict__ w_in,
                                               const float* __restrict__ b_in) {
    int b = blockIdx.x;
    int t = threadIdx.x;
    __shared__ float r_s[CH], alpha_s[CH], beta_s[CH];
    if (t < CH) {
        r_s[t] = g_r[b][t];
        alpha_s[t] = g_S[b][t][t];   // temp sumsq holder
    }
    __syncthreads();
    if (t < CH) {
        int g0 = (t >> 4) << 4;
        float sum = 0.f, sumsq = 0.f;
        #pragma unroll
        for (int i = 0; i < GSIZE; ++i) { sum += r_s[g0 + i]; sumsq += alpha_s[g0 + i]; }
        const float inv_cnt = 1.f / (float)(GSIZE * SP);
        float mu  = sum * inv_cnt;
        float var = sumsq * inv_cnt - mu * mu;
        float al = gn_w[t] * rsqrtf(var + EPS);
        beta_s[t] = gn_b[t] - mu * al;
        g_alpha[b][t] = al;
    }
    __syncthreads();
    if (t < CH) alpha_s[t] = g_alpha[b][t];
    __syncthreads();
    {
        int o = t >> 2, q = t & 3;
        const float* wrow = w_in + o * CH + q * 32;
        float bp = 0.f, uu = 0.f;
        #pragma unroll 8
        for (int c = 0; c < 32; ++c) {
            float w = wrow[c];
            int cc = q * 32 + c;
            bp += w * beta_s[cc];
            uu += w * alpha_s[cc] * r_s[cc];
        }
        bp += __shfl_xor_sync(0xFFFFFFFF, bp, 1);
        uu += __shfl_xor_sync(0xFFFFFFFF, uu, 1);
        bp += __shfl_xor_sync(0xFFFFFFFF, bp, 2);
        uu += __shfl_xor_sync(0xFFFFFFFF, uu, 2);
        if (q == 0) {
            g_Bp[b][o] = bp + b_in[o];
            g_u[b][o]  = uu;
        }
    }
}

// ================= prep2: Gram -> softmax -> M (1024 thr, S staged) ============
#define P2_SF   (128*132)
#define P2_WF   (16*132)
#define P2_SMEM ((P2_SF + 2*P2_WF + 2*16*17) * 4)
__global__ __launch_bounds__(1024) void k_prep2(const float* __restrict__ w_in,
                                                const float* __restrict__ w_out) {
    extern __shared__ float sm2[];
    float* Ss  = sm2;
    float* Whs = Ss + P2_SF;
    float* Ts  = Whs + P2_WF;
    float* sc  = Ts + P2_WF;
    float* Wt  = sc + 16*17;
    uint32_t sb = smem_u32(sm2);

    int b = blockIdx.x >> 3, h = blockIdx.x & 7;
    int t = threadIdx.x;

    #pragma unroll
    for (int w = 0; w < 4; ++w) {
        int m = t + 1024*w;
        int row = m >> 5, c16 = m & 31;
        CP_ASYNC16(sb + (uint32_t)(row*132 + 4*c16)*4, &g_S[b][row][4*c16]);
    }
    CP_COMMIT();
    for (int idx = t; idx < 16 * CH; idx += 1024) {
        int i = idx >> 7, k = idx & 127;
        Whs[i*132 + k] = w_in[(h*16 + i)*CH + k] * g_alpha[b][k];
    }
    CP_WAIT0();
    __syncthreads();

    {
        int l = t >> 3, i0 = t & 7;
        float ta0 = 0.f, ta1 = 0.f;
        #pragma unroll 4
        for (int k4 = 0; k4 < 32; ++k4) {
            float4 sv = *(const float4*)&Ss[l*132 + 4*k4];
            float4 w0 = *(const float4*)&Whs[i0*132 + 4*k4];
            float4 w1 = *(const float4*)&Whs[(i0 + 8)*132 + 4*k4];
            ta0 += w0.x*sv.x + w0.y*sv.y + w0.z*sv.z + w0.w*sv.w;
            ta1 += w1.x*sv.x + w1.y*sv.y + w1.z*sv.z + w1.w*sv.w;
        }
        Ts[i0*132 + l]       = ta0;
        Ts[(i0 + 8)*132 + l] = ta1;
    }
    __syncthreads();

    if (t < 256) {
        int i = t >> 4, j = t & 15;
        float g = 0.f;
        #pragma unroll 4
        for (int l4 = 0; l4 < 32; ++l4) {
            float4 tv = *(const float4*)&Ts[i*132 + 4*l4];
            float4 wv = *(const float4*)&Whs[j*132 + 4*l4];
            g += tv.x*wv.x + tv.y*wv.y + tv.z*wv.z + tv.w*wv.w;
        }
        float ui = g_u[b][h*16 + i], bi = g_Bp[b][h*16 + i];
        float uj = g_u[b][h*16 + j], bj = g_Bp[b][h*16 + j];
        sc[i*17 + j] = 0.25f * (g + ui*bj + bi*uj + (float)SP * bi * bj);
    }
    __syncthreads();

    if (t < 16) {
        float m = sc[t*17 + 0];
        #pragma unroll
        for (int j = 1; j < 16; ++j) m = fmaxf(m, sc[t*17 + j]);
        float e[16], s = 0.f;
        #pragma unroll
        for (int j = 0; j < 16; ++j) { e[j] = expf(sc[t*17 + j] - m); s += e[j]; }
        float inv = 1.f / s;
        #pragma unroll
        for (int j = 0; j < 16; ++j) Wt[t*17 + j] = e[j] * inv;
    }
    __syncthreads();

    {
        int o = t >> 3, j0 = (t & 7) * 2;
        float m0 = 0.f, m1 = 0.f;
        const float* wrow = w_out + o*CH + h*16;
        #pragma unroll
        for (int i = 0; i < 16; ++i) {
            float wo = wrow[i];
            m0 += wo * Wt[i*17 + j0];
            m1 += wo * Wt[i*17 + j0 + 1];
        }
        g_M[b][o][h*16 + j0]     = m0;
        g_M[b][o][h*16 + j0 + 1] = m1;
    }
}

// ===== prep3: A = (M W' + I) bf16 hi/lo [o][c]; d = M B' + b_out (8 rows/blk) ==
__global__ __launch_bounds__(128) void k_prep3(const float* __restrict__ w_in,
                                               const float* __restrict__ b_out) {
    int b = blockIdx.y, o0 = blockIdx.x * 8;
    int t = threadIdx.x;  // = c
    __shared__ float Ms[8][CH];
    __shared__ float Bp_s[CH];
    for (int idx = t; idx < 8 * CH; idx += 128) {
        int i = idx >> 7, k = idx & 127;
        Ms[i][k] = g_M[b][o0 + i][k];
    }
    Bp_s[t] = g_Bp[b][t];
    __syncthreads();
    float a[8];
    #pragma unroll
    for (int i = 0; i < 8; ++i) a[i] = 0.f;
    for (int k = 0; k < CH; ++k) {
        float wv = w_in[k * CH + t];
        #pragma unroll
        for (int i = 0; i < 8; ++i) a[i] += Ms[i][k] * wv;
    }
    float al = g_alpha[b][t];
    #pragma unroll
    for (int i = 0; i < 8; ++i) {
        float v = al * a[i];
        if (o0 + i == t) v += 1.0f;
        __nv_bfloat16 hh = __float2bfloat16(v);
        g_Ahi[b][(o0 + i) * CH + t] = hh;
        g_Alo[b][(o0 + i) * CH + t] = __float2bfloat16(v - __bfloat162float(hh));
    }
    if (t < 8) {
        float dv = b_out[o0 + t];
        for (int k = 0; k < CH; ++k) dv += Ms[t][k] * Bp_s[k];
        g_d[b][o0 + t] = dv;
    }
}

// ================= main: out = (C+I) x + d via HMMA, 512 thr, ldmatrix ========
#define MA_AH  0                     // 128 x 272 B
#define MA_AL  34816
#define MA_XTH 69632                 // 64 x 272 B
#define MA_XTL 87040
#define MA_XS0 104448                // fp32 [128][68]
#define MA_XS1 139264
#define MA_DS  174080
#define MA_SMEM 174592
#define MA_NT 7
#define MA_BX 37
__global__ __launch_bounds__(512, 1) void k_main_mma2(const float* __restrict__ x,
                                                      float* __restrict__ out) {
    extern __shared__ __align__(16) char sm[];
    uint32_t sb = smem_u32(sm);
    int b = blockIdx.y, bx = blockIdx.x;
    int t = threadIdx.x;
    int wid = t >> 5, lane = t & 31, g = lane >> 2, tg = lane & 3;
    int m0 = (wid >> 2) * 32, n0 = (wid & 3) * 16;

    uint32_t aBase0 = (uint32_t)(m0 + (lane & 15)) * 272 + (lane >> 4) * 16;
    uint32_t aBase1 = aBase0 + 16 * 272;
    uint32_t bBase0 = (uint32_t)(n0 + (lane & 7)) * 272 + ((lane >> 3) & 1) * 16;
    uint32_t bBase1 = bBase0 + 8 * 272;

    const float* xb = x + (size_t)b * BSTRIDE;
    float* ob = out + (size_t)b * BSTRIDE;
    const float* ds = (const float*)(sm + MA_DS);

    {
        const char* Ah = (const char*)&g_Ahi[b][0];
        const char* Al = (const char*)&g_Alo[b][0];
        #pragma unroll
        for (int w = 0; w < 4; ++w) {
            int m = t + 512*w;
            int o = m >> 4, cg = m & 15;
            uint32_t doff = (uint32_t)o*272 + cg*16;
            CP_ASYNC16(sb + MA_AH + doff, Ah + m*16);
            CP_ASYNC16(sb + MA_AL + doff, Al + m*16);
        }
        if (t < 32) CP_ASYNC16(sb + MA_DS + t*16, (const char*)&g_d[b][0] + t*16);
        int st0 = bx;
        #pragma unroll
        for (int w = 0; w < 4; ++w) {
            int fidx = t + 512*w;
            int c = fidx >> 4, f4 = fidx & 15;
            CP_ASYNC16(sb + MA_XS0 + (uint32_t)(c*68 + 4*f4)*4,
                       xb + (size_t)c*SP + st0*64 + 4*f4);
        }
        CP_COMMIT();
    }

    for (int it = 0; it < MA_NT; ++it) {
        int st = bx + MA_BX*it;
        bool valid = st < 256;
        int buf = it & 1;
        if (it + 1 < MA_NT) {
            int stn = bx + MA_BX*(it+1);
            if (stn > 255) stn = 255;
            int nbuf = buf ^ 1;
            #pragma unroll
            for (int w = 0; w < 4; ++w) {
                int fidx = t + 512*w;
                int c = fidx >> 4, f4 = fidx & 15;
                CP_ASYNC16(sb + (nbuf ? MA_XS1 : MA_XS0) + (uint32_t)(c*68 + 4*f4)*4,
                           xb + (size_t)c*SP + stn*64 + 4*f4);
            }
            CP_COMMIT();
            CP_WAIT1();
        } else {
            CP_WAIT0();
        }
        __syncthreads();

        const float* xsB = (const float*)(sm + (buf ? MA_XS1 : MA_XS0));
        #pragma unroll
        for (int w = 0; w < 4; ++w) {
            int u = t + 512*w;
            int s = u & 63, c4 = u >> 6;
            float4 v;
            v.x = xsB[(4*c4 + 0)*68 + s];
            v.y = xsB[(4*c4 + 1)*68 + s];
            v.z = xsB[(4*c4 + 2)*68 + s];
            v.w = xsB[(4*c4 + 3)*68 + s];
            uint32_t h01, h23, l01, l23;
            split4(v, h01, h23, l01, l23);
            uint32_t off = (uint32_t)s*272 + c4*8;
            *(uint2*)(sm + MA_XTH + off) = make_uint2(h01, h23);
            *(uint2*)(sm + MA_XTL + off) = make_uint2(l01, l23);
        }
        __syncthreads();

        float acc[2][2][4];
        #pragma unroll
        for (int i = 0; i < 2; ++i)
            #pragma unroll
            for (int j = 0; j < 2; ++j)
                #pragma unroll
                for (int q = 0; q < 4; ++q) acc[i][j][q] = 0.f;

        #pragma unroll
        for (int k = 0; k < 8; ++k) {
            uint32_t koff = k * 32;
            uint32_t ah[2][4], al[2][4];
            ldmx4(ah[0], sb + MA_AH + aBase0 + koff);
            ldmx4(ah[1], sb + MA_AH + aBase1 + koff);
            ldmx4(al[0], sb + MA_AL + aBase0 + koff);
            ldmx4(al[1], sb + MA_AL + aBase1 + koff);
            uint32_t bh0[2], bh1[2], bl0[2], bl1[2];
            ldmx2(bh0, sb + MA_XTH + bBase0 + koff);
            ldmx2(bh1, sb + MA_XTH + bBase1 + koff);
            ldmx2(bl0, sb + MA_XTL + bBase0 + koff);
            ldmx2(bl1, sb + MA_XTL + bBase1 + koff);
            #pragma unroll
            for (int i = 0; i < 2; ++i) {
                mma16816(acc[i][0], ah[i][0], ah[i][1], ah[i][2], ah[i][3], bh0[0], bh0[1]);
                mma16816(acc[i][0], ah[i][0], ah[i][1], ah[i][2], ah[i][3], bl0[0], bl0[1]);
                mma16816(acc[i][0], al[i][0], al[i][1], al[i][2], al[i][3], bh0[0], bh0[1]);
                mma16816(acc[i][1], ah[i][0], ah[i][1], ah[i][2], ah[i][3], bh1[0], bh1[1]);
                mma16816(acc[i][1], ah[i][0], ah[i][1], ah[i][2], ah[i][3], bl1[0], bl1[1]);
                mma16816(acc[i][1], al[i][0], al[i][1], al[i][2], al[i][3], bh1[0], bh1[1]);
            }
        }

        if (valid) {
            int s0 = st * 64;
            #pragma unroll
            for (int i = 0; i < 2; ++i) {
                int r0 = m0 + 16*i + g, r1 = r0 + 8;
                float d0 = ds[r0], d1 = ds[r1];
                #pragma unroll
                for (int j = 0; j < 2; ++j) {
                    int scol = s0 + n0 + 8*j + 2*tg;
                    float2 v0 = { acc[i][j][0] + d0, acc[i][j][1] + d0 };
                    float2 v1 = { acc[i][j][2] + d1, acc[i][j][3] + d1 };
                    *(float2*)(ob + (size_t)r0 * SP + scol) = v0;
                    *(float2*)(ob + (size_t)r1 * SP + scol) = v1;
                }
            }
        }
    }
}

extern "C" void kernel_launch(void* const* d_in, const int* in_sizes, int n_in,
                              void* d_out, int out_size) {
    const float* x    = (const float*)d_in[0];
    const float* gn_w = (const float*)d_in[1];
    const float* gn_b = (const float*)d_in[2];
    const float* w_in = (const float*)d_in[3];
    const float* b_in = (const float*)d_in[4];
    const float* w_out= (const float*)d_in[5];
    const float* b_out= (const float*)d_in[6];
    float* out = (float*)d_out;
    (void)in_sizes; (void)n_in; (void)out_size;

    cudaFuncSetAttribute(k_syrk_mma,  cudaFuncAttributeMaxDynamicSharedMemorySize, SK_SMEM);
    cudaFuncSetAttribute(k_prep2,     cudaFuncAttributeMaxDynamicSharedMemorySize, P2_SMEM);
    cudaFuncSetAttribute(k_main_mma2, cudaFuncAttributeMaxDynamicSharedMemorySize, MA_SMEM);

    k_zero<<<512, 256>>>();
    k_syrk_mma<<<dim3(32, NB), 256, SK_SMEM>>>(x);
    k_prep1<<<NB, 512>>>(gn_w, gn_b, w_in, b_in);
    k_prep2<<<64, 1024, P2_SMEM>>>(w_in, w_out);
    k_prep3<<<dim3(16, NB), 128>>>(w_in, b_out);
    k_main_mma2<<<dim3(MA_BX, NB), 512, MA_SMEM>>>(x, out);
}

// round 14
// speedup vs baseline: 1.7222x; 1.0944x over previous
#include <cuda_runtime.h>
#include <cuda_bf16.h>
#include <cstdint>

#define CH 128
#define NB 8
#define SP 16384              // spatial = 128*128
#define BSTRIDE (CH*SP)
#define GSIZE 16
#define EPS 1e-5f

// ---------------- helpers ----------------
__device__ __forceinline__ uint32_t smem_u32(const void* p) {
    uint32_t a;
    asm("{ .reg .u64 t; cvta.to.shared.u64 t, %1; cvt.u32.u64 %0, t; }" : "=r"(a) : "l"(p));
    return a;
}
#define CP_ASYNC16(dst, src) \
    asm volatile("cp.async.cg.shared.global [%0], [%1], 16;" :: "r"(dst), "l"(src) : "memory")
#define CP_COMMIT() asm volatile("cp.async.commit_group;" ::: "memory")
#define CP_WAIT1()  asm volatile("cp.async.wait_group 1;" ::: "memory")
#define CP_WAIT0()  asm volatile("cp.async.wait_group 0;" ::: "memory")

__device__ __forceinline__ void mma16816(float* c, uint32_t a0, uint32_t a1,
                                         uint32_t a2, uint32_t a3,
                                         uint32_t b0, uint32_t b1) {
    asm volatile("mma.sync.aligned.m16n8k16.row.col.f32.bf16.bf16.f32 "
                 "{%0,%1,%2,%3}, {%4,%5,%6,%7}, {%8,%9}, {%0,%1,%2,%3};"
                 : "+f"(c[0]), "+f"(c[1]), "+f"(c[2]), "+f"(c[3])
                 : "r"(a0), "r"(a1), "r"(a2), "r"(a3), "r"(b0), "r"(b1));
}
__device__ __forceinline__ void ldmx4(uint32_t* r, uint32_t addr) {
    asm volatile("ldmatrix.sync.aligned.m8n8.x4.shared.b16 {%0,%1,%2,%3}, [%4];"
                 : "=r"(r[0]), "=r"(r[1]), "=r"(r[2]), "=r"(r[3]) : "r"(addr));
}
__device__ __forceinline__ void ldmx2(uint32_t* r, uint32_t addr) {
    asm volatile("ldmatrix.sync.aligned.m8n8.x2.shared.b16 {%0,%1}, [%2];"
                 : "=r"(r[0]), "=r"(r[1]) : "r"(addr));
}
__device__ __forceinline__ void ldmx2t(uint32_t* r, uint32_t addr) {
    asm volatile("ldmatrix.sync.aligned.m8n8.x2.trans.shared.b16 {%0,%1}, [%2];"
                 : "=r"(r[0]), "=r"(r[1]) : "r"(addr));
}

// fast packed split: 4 fp32 -> bf16x2 hi + lo words (pairs (x,y),(z,w))
__device__ __forceinline__ void split4(float4 v, uint32_t& h01, uint32_t& h23,
                                       uint32_t& l01, uint32_t& l23) {
    asm("cvt.rn.bf16x2.f32 %0, %1, %2;" : "=r"(h01) : "f"(v.y), "f"(v.x));
    asm("cvt.rn.bf16x2.f32 %0, %1, %2;" : "=r"(h23) : "f"(v.w), "f"(v.z));
    float hx = __uint_as_float(h01 << 16);
    float hy = __uint_as_float(h01 & 0xFFFF0000u);
    float hz = __uint_as_float(h23 << 16);
    float hw = __uint_as_float(h23 & 0xFFFF0000u);
    float lx = v.x - hx, ly = v.y - hy, lz = v.z - hz, lw = v.w - hw;
    asm("cvt.rn.bf16x2.f32 %0, %1, %2;" : "=r"(l01) : "f"(ly), "f"(lx));
    asm("cvt.rn.bf16x2.f32 %0, %1, %2;" : "=r"(l23) : "f"(lw), "f"(lz));
}

// ---------------- device scratch ----------------
__device__ float g_S[NB][CH][CH];
__device__ float g_r[NB][CH];
__device__ float g_alpha[NB][CH];
__device__ float g_Bp[NB][CH];
__device__ float g_u[NB][CH];
__device__ float g_M[NB][CH][CH];
__device__ __align__(16) __nv_bfloat16 g_Ahi[NB][CH*CH];  // (C+I)[o][c] hi
__device__ __align__(16) __nv_bfloat16 g_Alo[NB][CH*CH];  // (C+I)[o][c] lo
__device__ __align__(16) float g_d[NB][CH];
__device__ __align__(16) __nv_bfloat16 g_xh[(size_t)NB*BSTRIDE];  // x hi  [b][c][s]
__device__ __align__(16) __nv_bfloat16 g_xl[(size_t)NB*BSTRIDE];  // x lo  [b][c][s]

__global__ void k_zero() {
    int idx = blockIdx.x * blockDim.x + threadIdx.x;
    if (idx < NB*CH*CH) ((float*)g_S)[idx] = 0.f;
}

// ============ convert: x fp32 -> bf16 hi/lo, + exact row sums ============
// grid 1024 (one block per (b,c) row), 256 threads, 16 float4/thread
__global__ __launch_bounds__(256) void k_convert(const float* __restrict__ x) {
    int row = blockIdx.x;                      // b*CH + c
    const float4* src = (const float4*)(x + (size_t)row * SP);
    uint2* oh = (uint2*)(g_xh + (size_t)row * SP);
    uint2* ol = (uint2*)(g_xl + (size_t)row * SP);
    int t = threadIdx.x;
    float sum = 0.f;
    #pragma unroll 4
    for (int w = 0; w < 16; ++w) {
        int i = t + 256 * w;
        float4 v = src[i];
        sum += (v.x + v.y) + (v.z + v.w);
        uint32_t h01, h23, l01, l23;
        split4(v, h01, h23, l01, l23);
        oh[i] = make_uint2(h01, h23);
        ol[i] = make_uint2(l01, l23);
    }
    __shared__ float red[256];
    red[t] = sum;
    __syncthreads();
    #pragma unroll
    for (int s = 128; s > 0; s >>= 1) {
        if (t < s) red[t] += red[t + s];
        __syncthreads();
    }
    if (t == 0) g_r[row >> 7][row & 127] = red[0];
}

// ================= syrk via HMMA: S = X X^T (bf16 tiles direct) ===============
#define SK_XH  0                         // 128 rows x 144 B
#define SK_XL  18432
#define SK_BUF 36864                     // double-buffer stride
#define SK_SMEM 73728
__global__ __launch_bounds__(256, 2) void k_syrk_mma() {
    extern __shared__ __align__(16) char sm[];
    uint32_t sb = smem_u32(sm);
    int b = blockIdx.y;
    int chunk0 = blockIdx.x * 512;
    int t = threadIdx.x;
    int wid = t >> 5, lane = t & 31, g = lane >> 2, tg = lane & 3;
    int m0 = (wid >> 1) * 32, n0 = (wid & 1) * 64;

    uint32_t aBase0 = (uint32_t)(m0 + (lane & 15)) * 144 + (lane >> 4) * 16;
    uint32_t aBase1 = aBase0 + 16 * 144;
    uint32_t bBase[8];
    #pragma unroll
    for (int j = 0; j < 8; ++j)
        bBase[j] = (uint32_t)(n0 + 8*j + (lane & 7)) * 144 + ((lane >> 3) & 1) * 16;

    const __nv_bfloat16* xh = g_xh + (size_t)b * BSTRIDE + chunk0;
    const __nv_bfloat16* xl = g_xl + (size_t)b * BSTRIDE + chunk0;

    // prologue: tile 0 -> buf 0
    #pragma unroll
    for (int w = 0; w < 4; ++w) {
        int m = t + 256*w;                     // 1024 chunks per array
        int row = m >> 3, c16 = m & 7;
        uint32_t doff = (uint32_t)row*144 + c16*16;
        CP_ASYNC16(sb + SK_XH + doff, xh + (size_t)row*SP + c16*8);
        CP_ASYNC16(sb + SK_XL + doff, xl + (size_t)row*SP + c16*8);
    }
    CP_COMMIT();

    float acc[2][8][4];
    #pragma unroll
    for (int i = 0; i < 2; ++i)
        #pragma unroll
        for (int j = 0; j < 8; ++j)
            #pragma unroll
            for (int q = 0; q < 4; ++q) acc[i][j][q] = 0.f;

    for (int tile = 0; tile < 8; ++tile) {
        int buf = tile & 1;
        if (tile + 1 < 8) {
            uint32_t nb = sb + (buf ^ 1) * SK_BUF;
            #pragma unroll
            for (int w = 0; w < 4; ++w) {
                int m = t + 256*w;
                int row = m >> 3, c16 = m & 7;
                uint32_t doff = (uint32_t)row*144 + c16*16;
                CP_ASYNC16(nb + SK_XH + doff, xh + (size_t)row*SP + (tile+1)*64 + c16*8);
                CP_ASYNC16(nb + SK_XL + doff, xl + (size_t)row*SP + (tile+1)*64 + c16*8);
            }
            CP_COMMIT();
            CP_WAIT1();
        } else {
            CP_WAIT0();
        }
        __syncthreads();                 // this tile's data visible

        uint32_t base = sb + buf * SK_BUF;
        #pragma unroll
        for (int k = 0; k < 4; ++k) {
            uint32_t koff = k * 32;
            uint32_t ah[2][4], al[2][4];
            ldmx4(ah[0], base + SK_XH + aBase0 + koff);
            ldmx4(ah[1], base + SK_XH + aBase1 + koff);
            ldmx4(al[0], base + SK_XL + aBase0 + koff);
            ldmx4(al[1], base + SK_XL + aBase1 + koff);
            #pragma unroll
            for (int j = 0; j < 8; ++j) {
                uint32_t bh[2], bl[2];
                ldmx2(bh, base + SK_XH + bBase[j] + koff);
                ldmx2(bl, base + SK_XL + bBase[j] + koff);
                #pragma unroll
                for (int i = 0; i < 2; ++i) {
                    mma16816(acc[i][j], ah[i][0], ah[i][1], ah[i][2], ah[i][3], bh[0], bh[1]);
                    mma16816(acc[i][j], ah[i][0], ah[i][1], ah[i][2], ah[i][3], bl[0], bl[1]);
                    mma16816(acc[i][j], al[i][0], al[i][1], al[i][2], al[i][3], bh[0], bh[1]);
                }
            }
        }
        __syncthreads();                 // all warps done reading buf
    }

    #pragma unroll
    for (int i = 0; i < 2; ++i)
        #pragma unroll
        for (int j = 0; j < 8; ++j) {
            int r0 = m0 + 16*i + g, r1 = r0 + 8;
            int col = n0 + 8*j + 2*tg;
            atomicAdd(&g_S[b][r0][col],     acc[i][j][0]);
            atomicAdd(&g_S[b][r0][col + 1], acc[i][j][1]);
            atomicAdd(&g_S[b][r1][col],     acc[i][j][2]);
            atomicAdd(&g_S[b][r1][col + 1], acc[i][j][3]);
        }
}

// ================= prep1: GN stats, alpha/beta, B', u (512 thr) =================
__global__ __launch_bounds__(512) void k_prep1(const float* __restrict__ gn_w,
                                               const float* __restrict__ gn_b,
                                               const float* __restrict__ w_in,
                                               const float* __restrict__ b_in) {
    int b = blockIdx.x;
    int t = threadIdx.x;
    __shared__ float r_s[CH], alpha_s[CH], beta_s[CH];
    if (t < CH) {
        r_s[t] = g_r[b][t];
        alpha_s[t] = g_S[b][t][t];   // temp sumsq holder
    }
    __syncthreads();
    if (t < CH) {
        int g0 = (t >> 4) << 4;
        float sum = 0.f, sumsq = 0.f;
        #pragma unroll
        for (int i = 0; i < GSIZE; ++i) { sum += r_s[g0 + i]; sumsq += alpha_s[g0 + i]; }
        const float inv_cnt = 1.f / (float)(GSIZE * SP);
        float mu  = sum * inv_cnt;
        float var = sumsq * inv_cnt - mu * mu;
        float al = gn_w[t] * rsqrtf(var + EPS);
        beta_s[t] = gn_b[t] - mu * al;
        g_alpha[b][t] = al;
    }
    __syncthreads();
    if (t < CH) alpha_s[t] = g_alpha[b][t];
    __syncthreads();
    {
        int o = t >> 2, q = t & 3;
        const float* wrow = w_in + o * CH + q * 32;
        float bp = 0.f, uu = 0.f;
        #pragma unroll 8
        for (int c = 0; c < 32; ++c) {
            float w = wrow[c];
            int cc = q * 32 + c;
            bp += w * beta_s[cc];
            uu += w * alpha_s[cc] * r_s[cc];
        }
        bp += __shfl_xor_sync(0xFFFFFFFF, bp, 1);
        uu += __shfl_xor_sync(0xFFFFFFFF, uu, 1);
        bp += __shfl_xor_sync(0xFFFFFFFF, bp, 2);
        uu += __shfl_xor_sync(0xFFFFFFFF, uu, 2);
        if (q == 0) {
            g_Bp[b][o] = bp + b_in[o];
            g_u[b][o]  = uu;
        }
    }
}

// ================= prep2: Gram -> softmax -> M (1024 thr, S staged) ============
#define P2_SF   (128*132)
#define P2_WF   (16*132)
#define P2_SMEM ((P2_SF + 2*P2_WF + 2*16*17) * 4)
__global__ __launch_bounds__(1024) void k_prep2(const float* __restrict__ w_in,
                                                const float* __restrict__ w_out) {
    extern __shared__ float sm2[];
    float* Ss  = sm2;
    float* Whs = Ss + P2_SF;
    float* Ts  = Whs + P2_WF;
    float* sc  = Ts + P2_WF;
    float* Wt  = sc + 16*17;
    uint32_t sb = smem_u32(sm2);

    int b = blockIdx.x >> 3, h = blockIdx.x & 7;
    int t = threadIdx.x;

    #pragma unroll
    for (int w = 0; w < 4; ++w) {
        int m = t + 1024*w;
        int row = m >> 5, c16 = m & 31;
        CP_ASYNC16(sb + (uint32_t)(row*132 + 4*c16)*4, &g_S[b][row][4*c16]);
    }
    CP_COMMIT();
    for (int idx = t; idx < 16 * CH; idx += 1024) {
        int i = idx >> 7, k = idx & 127;
        Whs[i*132 + k] = w_in[(h*16 + i)*CH + k] * g_alpha[b][k];
    }
    CP_WAIT0();
    __syncthreads();

    {
        int l = t >> 3, i0 = t & 7;
        float ta0 = 0.f, ta1 = 0.f;
        #pragma unroll 4
        for (int k4 = 0; k4 < 32; ++k4) {
            float4 sv = *(const float4*)&Ss[l*132 + 4*k4];
            float4 w0 = *(const float4*)&Whs[i0*132 + 4*k4];
            float4 w1 = *(const float4*)&Whs[(i0 + 8)*132 + 4*k4];
            ta0 += w0.x*sv.x + w0.y*sv.y + w0.z*sv.z + w0.w*sv.w;
            ta1 += w1.x*sv.x + w1.y*sv.y + w1.z*sv.z + w1.w*sv.w;
        }
        Ts[i0*132 + l]       = ta0;
        Ts[(i0 + 8)*132 + l] = ta1;
    }
    __syncthreads();

    if (t < 256) {
        int i = t >> 4, j = t & 15;
        float g = 0.f;
        #pragma unroll 4
        for (int l4 = 0; l4 < 32; ++l4) {
            float4 tv = *(const float4*)&Ts[i*132 + 4*l4];
            float4 wv = *(const float4*)&Whs[j*132 + 4*l4];
            g += tv.x*wv.x + tv.y*wv.y + tv.z*wv.z + tv.w*wv.w;
        }
        float ui = g_u[b][h*16 + i], bi = g_Bp[b][h*16 + i];
        float uj = g_u[b][h*16 + j], bj = g_Bp[b][h*16 + j];
        sc[i*17 + j] = 0.25f * (g + ui*bj + bi*uj + (float)SP * bi * bj);
    }
    __syncthreads();

    if (t < 16) {
        float m = sc[t*17 + 0];
        #pragma unroll
        for (int j = 1; j < 16; ++j) m = fmaxf(m, sc[t*17 + j]);
        float e[16], s = 0.f;
        #pragma unroll
        for (int j = 0; j < 16; ++j) { e[j] = expf(sc[t*17 + j] - m); s += e[j]; }
        float inv = 1.f / s;
        #pragma unroll
        for (int j = 0; j < 16; ++j) Wt[t*17 + j] = e[j] * inv;
    }
    __syncthreads();

    {
        int o = t >> 3, j0 = (t & 7) * 2;
        float m0 = 0.f, m1 = 0.f;
        const float* wrow = w_out + o*CH + h*16;
        #pragma unroll
        for (int i = 0; i < 16; ++i) {
            float wo = wrow[i];
            m0 += wo * Wt[i*17 + j0];
            m1 += wo * Wt[i*17 + j0 + 1];
        }
        g_M[b][o][h*16 + j0]     = m0;
        g_M[b][o][h*16 + j0 + 1] = m1;
    }
}

// ===== prep3: A = (M W' + I) bf16 hi/lo [o][c]; d = M B' + b_out (8 rows/blk) ==
__global__ __launch_bounds__(128) void k_prep3(const float* __restrict__ w_in,
                                               const float* __restrict__ b_out) {
    int b = blockIdx.y, o0 = blockIdx.x * 8;
    int t = threadIdx.x;  // = c
    __shared__ float Ms[8][CH];
    __shared__ float Bp_s[CH];
    for (int idx = t; idx < 8 * CH; idx += 128) {
        int i = idx >> 7, k = idx & 127;
        Ms[i][k] = g_M[b][o0 + i][k];
    }
    Bp_s[t] = g_Bp[b][t];
    __syncthreads();
    float a[8];
    #pragma unroll
    for (int i = 0; i < 8; ++i) a[i] = 0.f;
    for (int k = 0; k < CH; ++k) {
        float wv = w_in[k * CH + t];
        #pragma unroll
        for (int i = 0; i < 8; ++i) a[i] += Ms[i][k] * wv;
    }
    float al = g_alpha[b][t];
    #pragma unroll
    for (int i = 0; i < 8; ++i) {
        float v = al * a[i];
        if (o0 + i == t) v += 1.0f;
        __nv_bfloat16 hh = __float2bfloat16(v);
        g_Ahi[b][(o0 + i) * CH + t] = hh;
        g_Alo[b][(o0 + i) * CH + t] = __float2bfloat16(v - __bfloat162float(hh));
    }
    if (t < 8) {
        float dv = b_out[o0 + t];
        for (int k = 0; k < CH; ++k) dv += Ms[t][k] * Bp_s[k];
        g_d[b][o0 + t] = dv;
    }
}

// ====== main: out = (C+I) x + d via HMMA; bf16 x direct, ldmatrix.trans B ======
#define MB_AH  0                     // 128 x 272 B
#define MB_AL  34816
#define MB_X   69632                 // 2 buffers x (XH 18432 + XL 18432)
#define MB_XH  0
#define MB_XL  18432
#define MB_BUF 36864
#define MB_DS  143360
#define MB_SMEM 143872
#define MB_NT 7
#define MB_BX 37
__global__ __launch_bounds__(512, 1) void k_main_mma3(float* __restrict__ out) {
    extern __shared__ __align__(16) char sm[];
    uint32_t sb = smem_u32(sm);
    int b = blockIdx.y, bx = blockIdx.x;
    int t = threadIdx.x;
    int wid = t >> 5, lane = t & 31, g = lane >> 2, tg = lane & 3;
    int m0 = (wid >> 2) * 32, n0 = (wid & 3) * 16;

    // A fragment bases (row-major [o][c], 272B rows)
    uint32_t aBase0 = (uint32_t)(m0 + (lane & 15)) * 272 + (lane >> 4) * 16;
    uint32_t aBase1 = aBase0 + 16 * 272;
    // B (trans) base: rows = c (144B stride), col offset = n (bf16)
    uint32_t bTr = (uint32_t)((lane & 7) + ((lane >> 3) & 1) * 8) * 144 + n0 * 2;

    const __nv_bfloat16* xh = g_xh + (size_t)b * BSTRIDE;
    const __nv_bfloat16* xl = g_xl + (size_t)b * BSTRIDE;
    float* ob = out + (size_t)b * BSTRIDE;
    const float* ds = (const float*)(sm + MB_DS);

    // prologue: A hi/lo + d + x tile0 (one commit group)
    {
        const char* Ah = (const char*)&g_Ahi[b][0];
        const char* Al = (const char*)&g_Alo[b][0];
        #pragma unroll
        for (int w = 0; w < 4; ++w) {
            int m = t + 512*w;
            int o = m >> 4, cg = m & 15;
            uint32_t doff = (uint32_t)o*272 + cg*16;
            CP_ASYNC16(sb + MB_AH + doff, Ah + m*16);
            CP_ASYNC16(sb + MB_AL + doff, Al + m*16);
        }
        if (t < 32) CP_ASYNC16(sb + MB_DS + t*16, (const char*)&g_d[b][0] + t*16);
        int st0 = bx;
        #pragma unroll
        for (int w = 0; w < 2; ++w) {
            int m = t + 512*w;                   // 1024 chunks per array
            int row = m >> 3, c16 = m & 7;
            uint32_t doff = (uint32_t)row*144 + c16*16;
            CP_ASYNC16(sb + MB_X + MB_XH + doff, xh + (size_t)row*SP + st0*64 + c16*8);
            CP_ASYNC16(sb + MB_X + MB_XL + doff, xl + (size_t)row*SP + st0*64 + c16*8);
        }
        CP_COMMIT();
    }

    for (int it = 0; it < MB_NT; ++it) {
        int st = bx + MB_BX*it;
        bool valid = st < 256;
        int buf = it & 1;
        if (it + 1 < MB_NT) {
            int stn = bx + MB_BX*(it+1);
            if (stn > 255) stn = 255;
            uint32_t nb = sb + MB_X + (buf ^ 1) * MB_BUF;
            #pragma unroll
            for (int w = 0; w < 2; ++w) {
                int m = t + 512*w;
                int row = m >> 3, c16 = m & 7;
                uint32_t doff = (uint32_t)row*144 + c16*16;
                CP_ASYNC16(nb + MB_XH + doff, xh + (size_t)row*SP + stn*64 + c16*8);
                CP_ASYNC16(nb + MB_XL + doff, xl + (size_t)row*SP + stn*64 + c16*8);
            }
            CP_COMMIT();
            CP_WAIT1();
        } else {
            CP_WAIT0();
        }
        __syncthreads();

        uint32_t xbase = sb + MB_X + buf * MB_BUF;
        float acc[2][2][4];
        #pragma unroll
        for (int i = 0; i < 2; ++i)
            #pragma unroll
            for (int j = 0; j < 2; ++j)
                #pragma unroll
                for (int q = 0; q < 4; ++q) acc[i][j][q] = 0.f;

        #pragma unroll
        for (int k = 0; k < 8; ++k) {
            uint32_t koffA = k * 32;             // 16 c x 2B in A rows
            uint32_t koffX = k * 16 * 144;       // 16 c rows in X
            uint32_t ah[2][4], al[2][4];
            ldmx4(ah[0], sb + MB_AH + aBase0 + koffA);
            ldmx4(ah[1], sb + MB_AH + aBase1 + koffA);
            ldmx4(al[0], sb + MB_AL + aBase0 + koffA);
            ldmx4(al[1], sb + MB_AL + aBase1 + koffA);
            #pragma unroll
            for (int j = 0; j < 2; ++j) {
                uint32_t bh[2], bl[2];
                ldmx2t(bh, xbase + MB_XH + bTr + koffX + j*16);
                ldmx2t(bl, xbase + MB_XL + bTr + koffX + j*16);
                #pragma unroll
                for (int i = 0; i < 2; ++i) {
                    mma16816(acc[i][j], ah[i][0], ah[i][1], ah[i][2], ah[i][3], bh[0], bh[1]);
                    mma16816(acc[i][j], ah[i][0], ah[i][1], ah[i][2], ah[i][3], bl[0], bl[1]);
                    mma16816(acc[i][j], al[i][0], al[i][1], al[i][2], al[i][3], bh[0], bh[1]);
                }
            }
        }

        if (valid) {
            int s0 = st * 64;
            #pragma unroll
            for (int i = 0; i < 2; ++i) {
                int r0 = m0 + 16*i + g, r1 = r0 + 8;
                float d0 = ds[r0], d1 = ds[r1];
                #pragma unroll
                for (int j = 0; j < 2; ++j) {
                    int scol = s0 + n0 + 8*j + 2*tg;
                    float2 v0 = { acc[i][j][0] + d0, acc[i][j][1] + d0 };
                    float2 v1 = { acc[i][j][2] + d1, acc[i][j][3] + d1 };
                    *(float2*)(ob + (size_t)r0 * SP + scol) = v0;
                    *(float2*)(ob + (size_t)r1 * SP + scol) = v1;
                }
            }
        }
        __syncthreads();                // all warps done reading buf
    }
}

extern "C" void kernel_launch(void* const* d_in, const int* in_sizes, int n_in,
                              void* d_out, int out_size) {
    const float* x    = (const float*)d_in[0];
    const float* gn_w = (const float*)d_in[1];
    const float* gn_b = (const float*)d_in[2];
    const float* w_in = (const float*)d_in[3];
    const float* b_in = (const float*)d_in[4];
    const float* w_out= (const float*)d_in[5];
    const float* b_out= (const float*)d_in[6];
    float* out = (float*)d_out;
    (void)in_sizes; (void)n_in; (void)out_size;

    cudaFuncSetAttribute(k_syrk_mma,  cudaFuncAttributeMaxDynamicSharedMemorySize, SK_SMEM);
    cudaFuncSetAttribute(k_prep2,     cudaFuncAttributeMaxDynamicSharedMemorySize, P2_SMEM);
    cudaFuncSetAttribute(k_main_mma3, cudaFuncAttributeMaxDynamicSharedMemorySize, MB_SMEM);

    k_zero<<<512, 256>>>();
    k_convert<<<NB * CH, 256>>>(x);
    k_syrk_mma<<<dim3(32, NB), 256, SK_SMEM>>>();
    k_prep1<<<NB, 512>>>(gn_w, gn_b, w_in, b_in);
    k_prep2<<<64, 1024, P2_SMEM>>>(w_in, w_out);
    k_prep3<<<dim3(16, NB), 128>>>(w_in, b_out);
    k_main_mma3<<<dim3(MB_BX, NB), 512, MB_SMEM>>>(out);
}

// round 16
// speedup vs baseline: 1.8229x; 1.0585x over previous
#include <cuda_runtime.h>
#include <cuda_bf16.h>
#include <cstdint>

#define CH 128
#define NB 8
#define SP 16384              // spatial = 128*128
#define BSTRIDE (CH*SP)
#define GSIZE 16
#define EPS 1e-5f

// ---------------- helpers ----------------
__device__ __forceinline__ uint32_t smem_u32(const void* p) {
    uint32_t a;
    asm("{ .reg .u64 t; cvta.to.shared.u64 t, %1; cvt.u32.u64 %0, t; }" : "=r"(a) : "l"(p));
    return a;
}
#define CP_ASYNC16(dst, src) \
    asm volatile("cp.async.cg.shared.global [%0], [%1], 16;" :: "r"(dst), "l"(src) : "memory")
#define CP_COMMIT() asm volatile("cp.async.commit_group;" ::: "memory")
#define CP_WAIT1()  asm volatile("cp.async.wait_group 1;" ::: "memory")
#define CP_WAIT0()  asm volatile("cp.async.wait_group 0;" ::: "memory")

__device__ __forceinline__ void mma16816(float* c, uint32_t a0, uint32_t a1,
                                         uint32_t a2, uint32_t a3,
                                         uint32_t b0, uint32_t b1) {
    asm volatile("mma.sync.aligned.m16n8k16.row.col.f32.bf16.bf16.f32 "
                 "{%0,%1,%2,%3}, {%4,%5,%6,%7}, {%8,%9}, {%0,%1,%2,%3};"
                 : "+f"(c[0]), "+f"(c[1]), "+f"(c[2]), "+f"(c[3])
                 : "r"(a0), "r"(a1), "r"(a2), "r"(a3), "r"(b0), "r"(b1));
}
__device__ __forceinline__ void ldmx4(uint32_t* r, uint32_t addr) {
    asm volatile("ldmatrix.sync.aligned.m8n8.x4.shared.b16 {%0,%1,%2,%3}, [%4];"
                 : "=r"(r[0]), "=r"(r[1]), "=r"(r[2]), "=r"(r[3]) : "r"(addr));
}
__device__ __forceinline__ void ldmx2(uint32_t* r, uint32_t addr) {
    asm volatile("ldmatrix.sync.aligned.m8n8.x2.shared.b16 {%0,%1}, [%2];"
                 : "=r"(r[0]), "=r"(r[1]) : "r"(addr));
}
__device__ __forceinline__ void ldmx2t(uint32_t* r, uint32_t addr) {
    asm volatile("ldmatrix.sync.aligned.m8n8.x2.trans.shared.b16 {%0,%1}, [%2];"
                 : "=r"(r[0]), "=r"(r[1]) : "r"(addr));
}

// fast packed split: 4 fp32 -> bf16x2 hi + lo words (pairs (x,y),(z,w))
__device__ __forceinline__ void split4(float4 v, uint32_t& h01, uint32_t& h23,
                                       uint32_t& l01, uint32_t& l23) {
    asm("cvt.rn.bf16x2.f32 %0, %1, %2;" : "=r"(h01) : "f"(v.y), "f"(v.x));
    asm("cvt.rn.bf16x2.f32 %0, %1, %2;" : "=r"(h23) : "f"(v.w), "f"(v.z));
    float hx = __uint_as_float(h01 << 16);
    float hy = __uint_as_float(h01 & 0xFFFF0000u);
    float hz = __uint_as_float(h23 << 16);
    float hw = __uint_as_float(h23 & 0xFFFF0000u);
    float lx = v.x - hx, ly = v.y - hy, lz = v.z - hz, lw = v.w - hw;
    asm("cvt.rn.bf16x2.f32 %0, %1, %2;" : "=r"(l01) : "f"(ly), "f"(lx));
    asm("cvt.rn.bf16x2.f32 %0, %1, %2;" : "=r"(l23) : "f"(lw), "f"(lz));
}

// ---------------- device scratch ----------------
__device__ float g_S[NB][CH][CH];
__device__ float g_r[NB][CH];
__device__ float g_alpha[NB][CH];
__device__ float g_Bp[NB][CH];
__device__ float g_u[NB][CH];
__device__ float g_M[NB][CH][CH];
__device__ __align__(16) __nv_bfloat16 g_Ahi[NB][CH*CH];  // (C+I)[o][c] hi
__device__ __align__(16) __nv_bfloat16 g_Alo[NB][CH*CH];  // (C+I)[o][c] lo
__device__ __align__(16) float g_d[NB][CH];
__device__ __align__(16) __nv_bfloat16 g_xh[(size_t)NB*BSTRIDE];  // x hi  [b][c][s]
__device__ __align__(16) __nv_bfloat16 g_xl[(size_t)NB*BSTRIDE];  // x lo  [b][c][s]

// ============ convert: x fp32 -> bf16 hi/lo, + exact row sums; zero g_S ========
// grid 1024 (one block per (b,c) row), 256 threads, 16 float4/thread
__global__ __launch_bounds__(256) void k_convert(const float* __restrict__ x) {
    int row = blockIdx.x;                      // b*CH + c
    const float4* src = (const float4*)(x + (size_t)row * SP);
    uint2* oh = (uint2*)(g_xh + (size_t)row * SP);
    uint2* ol = (uint2*)(g_xl + (size_t)row * SP);
    int t = threadIdx.x;
    if (t < 128) ((float*)g_S)[(size_t)row * 128 + t] = 0.f;   // folded k_zero
    float sum = 0.f;
    #pragma unroll 4
    for (int w = 0; w < 16; ++w) {
        int i = t + 256 * w;
        float4 v = src[i];
        sum += (v.x + v.y) + (v.z + v.w);
        uint32_t h01, h23, l01, l23;
        split4(v, h01, h23, l01, l23);
        oh[i] = make_uint2(h01, h23);
        ol[i] = make_uint2(l01, l23);
    }
    __shared__ float red[256];
    red[t] = sum;
    __syncthreads();
    #pragma unroll
    for (int s = 128; s > 0; s >>= 1) {
        if (t < s) red[t] += red[t + s];
        __syncthreads();
    }
    if (t == 0) g_r[row >> 7][row & 127] = red[0];
}

// ================= syrk via HMMA: S = X X^T (bf16 tiles direct) ===============
#define SK_XH  0                         // 128 rows x 144 B
#define SK_XL  18432
#define SK_BUF 36864                     // double-buffer stride
#define SK_SMEM 73728
__global__ __launch_bounds__(256, 2) void k_syrk_mma() {
    extern __shared__ __align__(16) char sm[];
    uint32_t sb = smem_u32(sm);
    int b = blockIdx.y;
    int chunk0 = blockIdx.x * 512;
    int t = threadIdx.x;
    int wid = t >> 5, lane = t & 31, g = lane >> 2, tg = lane & 3;
    int m0 = (wid >> 1) * 32, n0 = (wid & 1) * 64;

    uint32_t aBase0 = (uint32_t)(m0 + (lane & 15)) * 144 + (lane >> 4) * 16;
    uint32_t aBase1 = aBase0 + 16 * 144;
    uint32_t bBase[8];
    #pragma unroll
    for (int j = 0; j < 8; ++j)
        bBase[j] = (uint32_t)(n0 + 8*j + (lane & 7)) * 144 + ((lane >> 3) & 1) * 16;

    const __nv_bfloat16* xh = g_xh + (size_t)b * BSTRIDE + chunk0;
    const __nv_bfloat16* xl = g_xl + (size_t)b * BSTRIDE + chunk0;

    #pragma unroll
    for (int w = 0; w < 4; ++w) {
        int m = t + 256*w;
        int row = m >> 3, c16 = m & 7;
        uint32_t doff = (uint32_t)row*144 + c16*16;
        CP_ASYNC16(sb + SK_XH + doff, xh + (size_t)row*SP + c16*8);
        CP_ASYNC16(sb + SK_XL + doff, xl + (size_t)row*SP + c16*8);
    }
    CP_COMMIT();

    float acc[2][8][4];
    #pragma unroll
    for (int i = 0; i < 2; ++i)
        #pragma unroll
        for (int j = 0; j < 8; ++j)
            #pragma unroll
            for (int q = 0; q < 4; ++q) acc[i][j][q] = 0.f;

    for (int tile = 0; tile < 8; ++tile) {
        int buf = tile & 1;
        if (tile + 1 < 8) {
            uint32_t nb = sb + (buf ^ 1) * SK_BUF;
            #pragma unroll
            for (int w = 0; w < 4; ++w) {
                int m = t + 256*w;
                int row = m >> 3, c16 = m & 7;
                uint32_t doff = (uint32_t)row*144 + c16*16;
                CP_ASYNC16(nb + SK_XH + doff, xh + (size_t)row*SP + (tile+1)*64 + c16*8);
                CP_ASYNC16(nb + SK_XL + doff, xl + (size_t)row*SP + (tile+1)*64 + c16*8);
            }
            CP_COMMIT();
            CP_WAIT1();
        } else {
            CP_WAIT0();
        }
        __syncthreads();

        uint32_t base = sb + buf * SK_BUF;
        #pragma unroll
        for (int k = 0; k < 4; ++k) {
            uint32_t koff = k * 32;
            uint32_t ah[2][4], al[2][4];
            ldmx4(ah[0], base + SK_XH + aBase0 + koff);
            ldmx4(ah[1], base + SK_XH + aBase1 + koff);
            ldmx4(al[0], base + SK_XL + aBase0 + koff);
            ldmx4(al[1], base + SK_XL + aBase1 + koff);
            #pragma unroll
            for (int j = 0; j < 8; ++j) {
                uint32_t bh[2], bl[2];
                ldmx2(bh, base + SK_XH + bBase[j] + koff);
                ldmx2(bl, base + SK_XL + bBase[j] + koff);
                #pragma unroll
                for (int i = 0; i < 2; ++i) {
                    mma16816(acc[i][j], ah[i][0], ah[i][1], ah[i][2], ah[i][3], bh[0], bh[1]);
                    mma16816(acc[i][j], ah[i][0], ah[i][1], ah[i][2], ah[i][3], bl[0], bl[1]);
                    mma16816(acc[i][j], al[i][0], al[i][1], al[i][2], al[i][3], bh[0], bh[1]);
                }
            }
        }
        __syncthreads();
    }

    #pragma unroll
    for (int i = 0; i < 2; ++i)
        #pragma unroll
        for (int j = 0; j < 8; ++j) {
            int r0 = m0 + 16*i + g, r1 = r0 + 8;
            int col = n0 + 8*j + 2*tg;
            atomicAdd(&g_S[b][r0][col],     acc[i][j][0]);
            atomicAdd(&g_S[b][r0][col + 1], acc[i][j][1]);
            atomicAdd(&g_S[b][r1][col],     acc[i][j][2]);
            atomicAdd(&g_S[b][r1][col + 1], acc[i][j][3]);
        }
}

// ====== prep1: GN stats, alpha/beta, B', u — coalesced warp-per-o ======
__global__ __launch_bounds__(512) void k_prep1(const float* __restrict__ gn_w,
                                               const float* __restrict__ gn_b,
                                               const float* __restrict__ w_in,
                                               const float* __restrict__ b_in) {
    int b = blockIdx.x;
    int t = threadIdx.x;
    __shared__ float r_s[CH], sq_s[CH], beta_s[CH], ar_s[CH];
    if (t < CH) {
        r_s[t]  = g_r[b][t];
        sq_s[t] = g_S[b][t][t];
    }
    __syncthreads();
    if (t < CH) {
        int g0 = (t >> 4) << 4;
        float sum = 0.f, sumsq = 0.f;
        #pragma unroll
        for (int i = 0; i < GSIZE; ++i) { sum += r_s[g0 + i]; sumsq += sq_s[g0 + i]; }
        const float inv_cnt = 1.f / (float)(GSIZE * SP);
        float mu  = sum * inv_cnt;
        float var = sumsq * inv_cnt - mu * mu;
        float al = gn_w[t] * rsqrtf(var + EPS);
        g_alpha[b][t] = al;
        beta_s[t] = gn_b[t] - mu * al;
        ar_s[t]   = al * r_s[t];
    }
    __syncthreads();
    // B'[o] = b_in[o] + sum_c w_in[o][c] beta[c];  u[o] = sum_c w_in[o][c] (alpha r)[c]
    // warp w handles o = w + 16p; lanes over contiguous c (coalesced)
    int w = t >> 5, lane = t & 31;
    #pragma unroll 2
    for (int p = 0; p < 8; ++p) {
        int o = w + 16 * p;
        const float* wrow = w_in + o * CH;
        float bp = 0.f, uu = 0.f;
        #pragma unroll
        for (int cc = 0; cc < 4; ++cc) {
            int c = lane + 32 * cc;
            float wv = wrow[c];
            bp += wv * beta_s[c];
            uu += wv * ar_s[c];
        }
        #pragma unroll
        for (int s = 16; s > 0; s >>= 1) {
            bp += __shfl_xor_sync(0xFFFFFFFF, bp, s);
            uu += __shfl_xor_sync(0xFFFFFFFF, uu, s);
        }
        if (lane == 0) {
            g_Bp[b][o] = bp + b_in[o];
            g_u[b][o]  = uu;
        }
    }
}

// ================= prep2: Gram -> softmax -> M (1024 thr, S staged) ============
#define P2_SF   (128*132)
#define P2_WF   (16*132)
#define P2_SMEM ((P2_SF + 2*P2_WF + 2*16*17) * 4)
__global__ __launch_bounds__(1024) void k_prep2(const float* __restrict__ w_in,
                                                const float* __restrict__ w_out) {
    extern __shared__ float sm2[];
    float* Ss  = sm2;
    float* Whs = Ss + P2_SF;
    float* Ts  = Whs + P2_WF;
    float* sc  = Ts + P2_WF;
    float* Wt  = sc + 16*17;
    uint32_t sb = smem_u32(sm2);

    int b = blockIdx.x >> 3, h = blockIdx.x & 7;
    int t = threadIdx.x;

    #pragma unroll
    for (int w = 0; w < 4; ++w) {
        int m = t + 1024*w;
        int row = m >> 5, c16 = m & 31;
        CP_ASYNC16(sb + (uint32_t)(row*132 + 4*c16)*4, &g_S[b][row][4*c16]);
    }
    CP_COMMIT();
    for (int idx = t; idx < 16 * CH; idx += 1024) {
        int i = idx >> 7, k = idx & 127;
        Whs[i*132 + k] = w_in[(h*16 + i)*CH + k] * g_alpha[b][k];
    }
    CP_WAIT0();
    __syncthreads();

    {
        int l = t >> 3, i0 = t & 7;
        float ta0 = 0.f, ta1 = 0.f;
        #pragma unroll 4
        for (int k4 = 0; k4 < 32; ++k4) {
            float4 sv = *(const float4*)&Ss[l*132 + 4*k4];
            float4 w0 = *(const float4*)&Whs[i0*132 + 4*k4];
            float4 w1 = *(const float4*)&Whs[(i0 + 8)*132 + 4*k4];
            ta0 += w0.x*sv.x + w0.y*sv.y + w0.z*sv.z + w0.w*sv.w;
            ta1 += w1.x*sv.x + w1.y*sv.y + w1.z*sv.z + w1.w*sv.w;
        }
        Ts[i0*132 + l]       = ta0;
        Ts[(i0 + 8)*132 + l] = ta1;
    }
    __syncthreads();

    if (t < 256) {
        int i = t >> 4, j = t & 15;
        float g = 0.f;
        #pragma unroll 4
        for (int l4 = 0; l4 < 32; ++l4) {
            float4 tv = *(const float4*)&Ts[i*132 + 4*l4];
            float4 wv = *(const float4*)&Whs[j*132 + 4*l4];
            g += tv.x*wv.x + tv.y*wv.y + tv.z*wv.z + tv.w*wv.w;
        }
        float ui = g_u[b][h*16 + i], bi = g_Bp[b][h*16 + i];
        float uj = g_u[b][h*16 + j], bj = g_Bp[b][h*16 + j];
        sc[i*17 + j] = 0.25f * (g + ui*bj + bi*uj + (float)SP * bi * bj);
    }
    __syncthreads();

    if (t < 16) {
        float m = sc[t*17 + 0];
        #pragma unroll
        for (int j = 1; j < 16; ++j) m = fmaxf(m, sc[t*17 + j]);
        float e[16], s = 0.f;
        #pragma unroll
        for (int j = 0; j < 16; ++j) { e[j] = expf(sc[t*17 + j] - m); s += e[j]; }
        float inv = 1.f / s;
        #pragma unroll
        for (int j = 0; j < 16; ++j) Wt[t*17 + j] = e[j] * inv;
    }
    __syncthreads();

    {
        int o = t >> 3, j0 = (t & 7) * 2;
        float m0 = 0.f, m1 = 0.f;
        const float* wrow = w_out + o*CH + h*16;
        #pragma unroll
        for (int i = 0; i < 16; ++i) {
            float wo = wrow[i];
            m0 += wo * Wt[i*17 + j0];
            m1 += wo * Wt[i*17 + j0 + 1];
        }
        g_M[b][o][h*16 + j0]     = m0;
        g_M[b][o][h*16 + j0 + 1] = m1;
    }
}

// ===== prep3: A = (M W' + I) bf16 hi/lo [o][c]; d = M B' + b_out (8 rows/blk) ==
__global__ __launch_bounds__(128) void k_prep3(const float* __restrict__ w_in,
                                               const float* __restrict__ b_out) {
    int b = blockIdx.y, o0 = blockIdx.x * 8;
    int t = threadIdx.x;  // = c
    __shared__ float Ms[8][CH];
    __shared__ float Bp_s[CH];
    for (int idx = t; idx < 8 * CH; idx += 128) {
        int i = idx >> 7, k = idx & 127;
        Ms[i][k] = g_M[b][o0 + i][k];
    }
    Bp_s[t] = g_Bp[b][t];
    __syncthreads();
    float a[8];
    #pragma unroll
    for (int i = 0; i < 8; ++i) a[i] = 0.f;
    for (int k = 0; k < CH; ++k) {
        float wv = w_in[k * CH + t];
        #pragma unroll
        for (int i = 0; i < 8; ++i) a[i] += Ms[i][k] * wv;
    }
    float al = g_alpha[b][t];
    #pragma unroll
    for (int i = 0; i < 8; ++i) {
        float v = al * a[i];
        if (o0 + i == t) v += 1.0f;
        __nv_bfloat16 hh = __float2bfloat16(v);
        g_Ahi[b][(o0 + i) * CH + t] = hh;
        g_Alo[b][(o0 + i) * CH + t] = __float2bfloat16(v - __bfloat162float(hh));
    }
    if (t < 8) {
        float dv = b_out[o0 + t];
        for (int k = 0; k < CH; ++k) dv += Ms[t][k] * Bp_s[k];
        g_d[b][o0 + t] = dv;
    }
}

// ====== main: out = (C+I) x + d via HMMA; bf16 x direct, ldmatrix.trans B ======
#define MB_AH  0                     // 128 x 272 B
#define MB_AL  34816
#define MB_X   69632                 // 2 buffers x (XH 18432 + XL 18432)
#define MB_XH  0
#define MB_XL  18432
#define MB_BUF 36864
#define MB_DS  143360
#define MB_SMEM 143872
#define MB_NT 7
#define MB_BX 37
__global__ __launch_bounds__(512, 1) void k_main_mma3(float* __restrict__ out) {
    extern __shared__ __align__(16) char sm[];
    uint32_t sb = smem_u32(sm);
    int b = blockIdx.y, bx = blockIdx.x;
    int t = threadIdx.x;
    int wid = t >> 5, lane = t & 31, g = lane >> 2, tg = lane & 3;
    int m0 = (wid >> 2) * 32, n0 = (wid & 3) * 16;

    uint32_t aBase0 = (uint32_t)(m0 + (lane & 15)) * 272 + (lane >> 4) * 16;
    uint32_t aBase1 = aBase0 + 16 * 272;
    uint32_t bTr = (uint32_t)((lane & 7) + ((lane >> 3) & 1) * 8) * 144 + n0 * 2;

    const __nv_bfloat16* xh = g_xh + (size_t)b * BSTRIDE;
    const __nv_bfloat16* xl = g_xl + (size_t)b * BSTRIDE;
    float* ob = out + (size_t)b * BSTRIDE;
    const float* ds = (const float*)(sm + MB_DS);

    {
        const char* Ah = (const char*)&g_Ahi[b][0];
        const char* Al = (const char*)&g_Alo[b][0];
        #pragma unroll
        for (int w = 0; w < 4; ++w) {
            int m = t + 512*w;
            int o = m >> 4, cg = m & 15;
            uint32_t doff = (uint32_t)o*272 + cg*16;
            CP_ASYNC16(sb + MB_AH + doff, Ah + m*16);
            CP_ASYNC16(sb + MB_AL + doff, Al + m*16);
        }
        if (t < 32) CP_ASYNC16(sb + MB_DS + t*16, (const char*)&g_d[b][0] + t*16);
        int st0 = bx;
        #pragma unroll
        for (int w = 0; w < 2; ++w) {
            int m = t + 512*w;
            int row = m >> 3, c16 = m & 7;
            uint32_t doff = (uint32_t)row*144 + c16*16;
            CP_ASYNC16(sb + MB_X + MB_XH + doff, xh + (size_t)row*SP + st0*64 + c16*8);
            CP_ASYNC16(sb + MB_X + MB_XL + doff, xl + (size_t)row*SP + st0*64 + c16*8);
        }
        CP_COMMIT();
    }

    for (int it = 0; it < MB_NT; ++it) {
        int st = bx + MB_BX*it;
        bool valid = st < 256;
        int buf = it & 1;
        if (it + 1 < MB_NT) {
            int stn = bx + MB_BX*(it+1);
            if (stn > 255) stn = 255;
            uint32_t nb = sb + MB_X + (buf ^ 1) * MB_BUF;
            #pragma unroll
            for (int w = 0; w < 2; ++w) {
                int m = t + 512*w;
                int row = m >> 3, c16 = m & 7;
                uint32_t doff = (uint32_t)row*144 + c16*16;
                CP_ASYNC16(nb + MB_XH + doff, xh + (size_t)row*SP + stn*64 + c16*8);
                CP_ASYNC16(nb + MB_XL + doff, xl + (size_t)row*SP + stn*64 + c16*8);
            }
            CP_COMMIT();
            CP_WAIT1();
        } else {
            CP_WAIT0();
        }
        __syncthreads();

        uint32_t xbase = sb + MB_X + buf * MB_BUF;
        float acc[2][2][4];
        #pragma unroll
        for (int i = 0; i < 2; ++i)
            #pragma unroll
            for (int j = 0; j < 2; ++j)
                #pragma unroll
                for (int q = 0; q < 4; ++q) acc[i][j][q] = 0.f;

        #pragma unroll
        for (int k = 0; k < 8; ++k) {
            uint32_t koffA = k * 32;
            uint32_t koffX = k * 16 * 144;
            uint32_t ah[2][4], al[2][4];
            ldmx4(ah[0], sb + MB_AH + aBase0 + koffA);
            ldmx4(ah[1], sb + MB_AH + aBase1 + koffA);
            ldmx4(al[0], sb + MB_AL + aBase0 + koffA);
            ldmx4(al[1], sb + MB_AL + aBase1 + koffA);
            #pragma unroll
            for (int j = 0; j < 2; ++j) {
                uint32_t bh[2], bl[2];
                ldmx2t(bh, xbase + MB_XH + bTr + koffX + j*16);
                ldmx2t(bl, xbase + MB_XL + bTr + koffX + j*16);
                #pragma unroll
                for (int i = 0; i < 2; ++i) {
                    mma16816(acc[i][j], ah[i][0], ah[i][1], ah[i][2], ah[i][3], bh[0], bh[1]);
                    mma16816(acc[i][j], ah[i][0], ah[i][1], ah[i][2], ah[i][3], bl[0], bl[1]);
                    mma16816(acc[i][j], al[i][0], al[i][1], al[i][2], al[i][3], bh[0], bh[1]);
                }
            }
        }

        if (valid) {
            int s0 = st * 64;
            #pragma unroll
            for (int i = 0; i < 2; ++i) {
                int r0 = m0 + 16*i + g, r1 = r0 + 8;
                float d0 = ds[r0], d1 = ds[r1];
                #pragma unroll
                for (int j = 0; j < 2; ++j) {
                    int scol = s0 + n0 + 8*j + 2*tg;
                    float2 v0 = { acc[i][j][0] + d0, acc[i][j][1] + d0 };
                    float2 v1 = { acc[i][j][2] + d1, acc[i][j][3] + d1 };
                    *(float2*)(ob + (size_t)r0 * SP + scol) = v0;
                    *(float2*)(ob + (size_t)r1 * SP + scol) = v1;
                }
            }
        }
        __syncthreads();
    }
}

extern "C" void kernel_launch(void* const* d_in, const int* in_sizes, int n_in,
                              void* d_out, int out_size) {
    const float* x    = (const float*)d_in[0];
    const float* gn_w = (const float*)d_in[1];
    const float* gn_b = (const float*)d_in[2];
    const float* w_in = (const float*)d_in[3];
    const float* b_in = (const float*)d_in[4];
    const float* w_out= (const float*)d_in[5];
    const float* b_out= (const float*)d_in[6];
    float* out = (float*)d_out;
    (void)in_sizes; (void)n_in; (void)out_size;

    cudaFuncSetAttribute(k_syrk_mma,  cudaFuncAttributeMaxDynamicSharedMemorySize, SK_SMEM);
    cudaFuncSetAttribute(k_prep2,     cudaFuncAttributeMaxDynamicSharedMemorySize, P2_SMEM);
    cudaFuncSetAttribute(k_main_mma3, cudaFuncAttributeMaxDynamicSharedMemorySize, MB_SMEM);

    k_convert<<<NB * CH, 256>>>(x);
    k_syrk_mma<<<dim3(32, NB), 256, SK_SMEM>>>();
    k_prep1<<<NB, 512>>>(gn_w, gn_b, w_in, b_in);
    k_prep2<<<64, 1024, P2_SMEM>>>(w_in, w_out);
    k_prep3<<<dim3(16, NB), 128>>>(w_in, b_out);
    k_main_mma3<<<dim3(MB_BX, NB), 512, MB_SMEM>>>(out);
}

// round 17
// speedup vs baseline: 1.9976x; 1.0958x over previous
#include <cuda_runtime.h>
#include <cuda_bf16.h>
#include <cstdint>

#define CH 128
#define NB 8
#define SP 16384              // spatial = 128*128
#define BSTRIDE (CH*SP)
#define GSIZE 16
#define EPS 1e-5f

// ---------------- helpers ----------------
__device__ __forceinline__ uint32_t smem_u32(const void* p) {
    uint32_t a;
    asm("{ .reg .u64 t; cvta.to.shared.u64 t, %1; cvt.u32.u64 %0, t; }" : "=r"(a) : "l"(p));
    return a;
}
#define CP_ASYNC16(dst, src) \
    asm volatile("cp.async.cg.shared.global [%0], [%1], 16;" :: "r"(dst), "l"(src) : "memory")
#define CP_COMMIT() asm volatile("cp.async.commit_group;" ::: "memory")
#define CP_WAIT1()  asm volatile("cp.async.wait_group 1;" ::: "memory")
#define CP_WAIT0()  asm volatile("cp.async.wait_group 0;" ::: "memory")

__device__ __forceinline__ void mma16816(float* c, uint32_t a0, uint32_t a1,
                                         uint32_t a2, uint32_t a3,
                                         uint32_t b0, uint32_t b1) {
    asm volatile("mma.sync.aligned.m16n8k16.row.col.f32.bf16.bf16.f32 "
                 "{%0,%1,%2,%3}, {%4,%5,%6,%7}, {%8,%9}, {%0,%1,%2,%3};"
                 : "+f"(c[0]), "+f"(c[1]), "+f"(c[2]), "+f"(c[3])
                 : "r"(a0), "r"(a1), "r"(a2), "r"(a3), "r"(b0), "r"(b1));
}
__device__ __forceinline__ void ldmx4(uint32_t* r, uint32_t addr) {
    asm volatile("ldmatrix.sync.aligned.m8n8.x4.shared.b16 {%0,%1,%2,%3}, [%4];"
                 : "=r"(r[0]), "=r"(r[1]), "=r"(r[2]), "=r"(r[3]) : "r"(addr));
}
__device__ __forceinline__ void ldmx2(uint32_t* r, uint32_t addr) {
    asm volatile("ldmatrix.sync.aligned.m8n8.x2.shared.b16 {%0,%1}, [%2];"
                 : "=r"(r[0]), "=r"(r[1]) : "r"(addr));
}
__device__ __forceinline__ void ldmx2t(uint32_t* r, uint32_t addr) {
    asm volatile("ldmatrix.sync.aligned.m8n8.x2.trans.shared.b16 {%0,%1}, [%2];"
                 : "=r"(r[0]), "=r"(r[1]) : "r"(addr));
}

// fast packed split: 4 fp32 -> bf16x2 hi + lo words (pairs (x,y),(z,w))
__device__ __forceinline__ void split4(float4 v, uint32_t& h01, uint32_t& h23,
                                       uint32_t& l01, uint32_t& l23) {
    asm("cvt.rn.bf16x2.f32 %0, %1, %2;" : "=r"(h01) : "f"(v.y), "f"(v.x));
    asm("cvt.rn.bf16x2.f32 %0, %1, %2;" : "=r"(h23) : "f"(v.w), "f"(v.z));
    float hx = __uint_as_float(h01 << 16);
    float hy = __uint_as_float(h01 & 0xFFFF0000u);
    float hz = __uint_as_float(h23 << 16);
    float hw = __uint_as_float(h23 & 0xFFFF0000u);
    float lx = v.x - hx, ly = v.y - hy, lz = v.z - hz, lw = v.w - hw;
    asm("cvt.rn.bf16x2.f32 %0, %1, %2;" : "=r"(l01) : "f"(ly), "f"(lx));
    asm("cvt.rn.bf16x2.f32 %0, %1, %2;" : "=r"(l23) : "f"(lw), "f"(lz));
}

// ---------------- device scratch ----------------
__device__ float g_S[NB][CH][CH];
__device__ float g_rp[NB][32][CH];    // per-chunk row-sum partials
__device__ float g_alpha[NB][CH];
__device__ float g_Bp[NB][CH];
__device__ float g_u[NB][CH];
__device__ float g_M[NB][CH][CH];
__device__ __align__(16) __nv_bfloat16 g_Ahi[NB][CH*CH];  // (C+I)[o][c] hi
__device__ __align__(16) __nv_bfloat16 g_Alo[NB][CH*CH];  // (C+I)[o][c] lo
__device__ __align__(16) float g_d[NB][CH];
__device__ __align__(16) __nv_bfloat16 g_xh[(size_t)NB*BSTRIDE];  // x hi  [b][c][s]
__device__ __align__(16) __nv_bfloat16 g_xl[(size_t)NB*BSTRIDE];  // x lo  [b][c][s]

__global__ void k_zero() {
    int idx = blockIdx.x * blockDim.x + threadIdx.x;
    ((float*)g_S)[idx] = 0.f;
}

// ===== syrk + convert fused: reads fp32 x once; S += X X^T; writes bf16 x =====
#define SK_XH  0                         // 128 rows x 144 B
#define SK_XL  18432
#define SK_XS0 36864                     // fp32 staging [128][68]
#define SK_XS1 71680
#define SK_SMEM 106496
__global__ __launch_bounds__(256, 2) void k_syrk_conv(const float* __restrict__ x) {
    extern __shared__ __align__(16) char sm[];
    uint32_t sb = smem_u32(sm);
    int b = blockIdx.y, ck = blockIdx.x;
    int chunk0 = ck * 512;
    int t = threadIdx.x;
    int wid = t >> 5, lane = t & 31, g = lane >> 2, tg = lane & 3;
    int m0 = (wid >> 1) * 32, n0 = (wid & 1) * 64;

    uint32_t aBase0 = (uint32_t)(m0 + (lane & 15)) * 144 + (lane >> 4) * 16;
    uint32_t aBase1 = aBase0 + 16 * 144;
    uint32_t bBase[8];
    #pragma unroll
    for (int j = 0; j < 8; ++j)
        bBase[j] = (uint32_t)(n0 + 8*j + (lane & 7)) * 144 + ((lane >> 3) & 1) * 16;

    const float* xb = x + (size_t)b * BSTRIDE + chunk0;

    // prologue: fp32 tile 0 -> XS0
    #pragma unroll
    for (int w = 0; w < 8; ++w) {
        int fidx = t + 256*w;
        int c = fidx >> 4, f4 = fidx & 15;
        CP_ASYNC16(sb + SK_XS0 + (uint32_t)(c*68 + 4*f4)*4, xb + (size_t)c*SP + 4*f4);
    }
    CP_COMMIT();

    float acc[2][8][4];
    #pragma unroll
    for (int i = 0; i < 2; ++i)
        #pragma unroll
        for (int j = 0; j < 8; ++j)
            #pragma unroll
            for (int q = 0; q < 4; ++q) acc[i][j][q] = 0.f;
    float rs[8];
    #pragma unroll
    for (int w = 0; w < 8; ++w) rs[w] = 0.f;

    for (int tile = 0; tile < 8; ++tile) {
        int buf = tile & 1;
        if (tile + 1 < 8) {
            uint32_t nb = sb + ((buf ^ 1) ? SK_XS1 : SK_XS0);
            #pragma unroll
            for (int w = 0; w < 8; ++w) {
                int fidx = t + 256*w;
                int c = fidx >> 4, f4 = fidx & 15;
                CP_ASYNC16(nb + (uint32_t)(c*68 + 4*f4)*4,
                           xb + (size_t)c*SP + (tile+1)*64 + 4*f4);
            }
            CP_COMMIT();
            CP_WAIT1();
        } else {
            CP_WAIT0();
        }
        __syncthreads();      // staged fp32 visible; prev mma done reading XH/XL

        // convert fp32 -> bf16 hi/lo: smem (for mma) + global (for k_main), + sums
        const float* xsB = (const float*)(sm + (buf ? SK_XS1 : SK_XS0));
        #pragma unroll
        for (int w = 0; w < 8; ++w) {
            int fidx = t + 256*w;
            int c = fidx >> 4, f4 = fidx & 15;
            float4 v = *(const float4*)(xsB + c*68 + 4*f4);
            rs[w] += (v.x + v.y) + (v.z + v.w);
            uint32_t h01, h23, l01, l23;
            split4(v, h01, h23, l01, l23);
            uint32_t off = (uint32_t)c*144 + f4*8;
            *(uint2*)(sm + SK_XH + off) = make_uint2(h01, h23);
            *(uint2*)(sm + SK_XL + off) = make_uint2(l01, l23);
            size_t gidx = (size_t)b*BSTRIDE + (size_t)c*SP + chunk0 + tile*64;
            ((uint2*)(g_xh + gidx))[f4] = make_uint2(h01, h23);
            ((uint2*)(g_xl + gidx))[f4] = make_uint2(l01, l23);
        }
        __syncthreads();

        #pragma unroll
        for (int k = 0; k < 4; ++k) {
            uint32_t koff = k * 32;
            uint32_t ah[2][4], al[2][4];
            ldmx4(ah[0], sb + SK_XH + aBase0 + koff);
            ldmx4(ah[1], sb + SK_XH + aBase1 + koff);
            ldmx4(al[0], sb + SK_XL + aBase0 + koff);
            ldmx4(al[1], sb + SK_XL + aBase1 + koff);
            #pragma unroll
            for (int j = 0; j < 8; ++j) {
                uint32_t bh[2], bl[2];
                ldmx2(bh, sb + SK_XH + bBase[j] + koff);
                ldmx2(bl, sb + SK_XL + bBase[j] + koff);
                #pragma unroll
                for (int i = 0; i < 2; ++i) {
                    mma16816(acc[i][j], ah[i][0], ah[i][1], ah[i][2], ah[i][3], bh[0], bh[1]);
                    mma16816(acc[i][j], ah[i][0], ah[i][1], ah[i][2], ah[i][3], bl[0], bl[1]);
                    mma16816(acc[i][j], al[i][0], al[i][1], al[i][2], al[i][3], bh[0], bh[1]);
                }
            }
        }
    }

    // flush S accumulators
    #pragma unroll
    for (int i = 0; i < 2; ++i)
        #pragma unroll
        for (int j = 0; j < 8; ++j) {
            int r0 = m0 + 16*i + g, r1 = r0 + 8;
            int col = n0 + 8*j + 2*tg;
            atomicAdd(&g_S[b][r0][col],     acc[i][j][0]);
            atomicAdd(&g_S[b][r0][col + 1], acc[i][j][1]);
            atomicAdd(&g_S[b][r1][col],     acc[i][j][2]);
            atomicAdd(&g_S[b][r1][col + 1], acc[i][j][3]);
        }
    // row-sum partials: reduce across the 16 lanes sharing each c, write g_rp
    #pragma unroll
    for (int s = 1; s < 16; s <<= 1) {
        #pragma unroll
        for (int w = 0; w < 8; ++w)
            rs[w] += __shfl_xor_sync(0xFFFFFFFF, rs[w], s);
    }
    if ((lane & 15) == 0) {
        int chalf = t >> 4;                 // 0..15, = wid*2 + (lane>>4)
        #pragma unroll
        for (int w = 0; w < 8; ++w)
            g_rp[b][ck][chalf + 16*w] = rs[w];
    }
}

// ====== prep1: GN stats, alpha/beta, B', u — coalesced warp-per-o ======
__global__ __launch_bounds__(512) void k_prep1(const float* __restrict__ gn_w,
                                               const float* __restrict__ gn_b,
                                               const float* __restrict__ w_in,
                                               const float* __restrict__ b_in) {
    int b = blockIdx.x;
    int t = threadIdx.x;
    __shared__ float r_s[CH], sq_s[CH], beta_s[CH], ar_s[CH];
    if (t < CH) {
        float s = 0.f;
        #pragma unroll 8
        for (int ck = 0; ck < 32; ++ck) s += g_rp[b][ck][t];
        r_s[t]  = s;
        sq_s[t] = g_S[b][t][t];
    }
    __syncthreads();
    if (t < CH) {
        int g0 = (t >> 4) << 4;
        float sum = 0.f, sumsq = 0.f;
        #pragma unroll
        for (int i = 0; i < GSIZE; ++i) { sum += r_s[g0 + i]; sumsq += sq_s[g0 + i]; }
        const float inv_cnt = 1.f / (float)(GSIZE * SP);
        float mu  = sum * inv_cnt;
        float var = sumsq * inv_cnt - mu * mu;
        float al = gn_w[t] * rsqrtf(var + EPS);
        g_alpha[b][t] = al;
        beta_s[t] = gn_b[t] - mu * al;
        ar_s[t]   = al * r_s[t];
    }
    __syncthreads();
    int w = t >> 5, lane = t & 31;
    #pragma unroll 2
    for (int p = 0; p < 8; ++p) {
        int o = w + 16 * p;
        const float* wrow = w_in + o * CH;
        float bp = 0.f, uu = 0.f;
        #pragma unroll
        for (int cc = 0; cc < 4; ++cc) {
            int c = lane + 32 * cc;
            float wv = wrow[c];
            bp += wv * beta_s[c];
            uu += wv * ar_s[c];
        }
        #pragma unroll
        for (int s = 16; s > 0; s >>= 1) {
            bp += __shfl_xor_sync(0xFFFFFFFF, bp, s);
            uu += __shfl_xor_sync(0xFFFFFFFF, uu, s);
        }
        if (lane == 0) {
            g_Bp[b][o] = bp + b_in[o];
            g_u[b][o]  = uu;
        }
    }
}

// ================= prep2: Gram -> softmax -> M (1024 thr, S staged) ============
#define P2_SF   (128*132)
#define P2_WF   (16*132)
#define P2_SMEM ((P2_SF + 2*P2_WF + 2*16*17) * 4)
__global__ __launch_bounds__(1024) void k_prep2(const float* __restrict__ w_in,
                                                const float* __restrict__ w_out) {
    extern __shared__ float sm2[];
    float* Ss  = sm2;
    float* Whs = Ss + P2_SF;
    float* Ts  = Whs + P2_WF;
    float* sc  = Ts + P2_WF;
    float* Wt  = sc + 16*17;
    uint32_t sb = smem_u32(sm2);

    int b = blockIdx.x >> 3, h = blockIdx.x & 7;
    int t = threadIdx.x;

    #pragma unroll
    for (int w = 0; w < 4; ++w) {
        int m = t + 1024*w;
        int row = m >> 5, c16 = m & 31;
        CP_ASYNC16(sb + (uint32_t)(row*132 + 4*c16)*4, &g_S[b][row][4*c16]);
    }
    CP_COMMIT();
    for (int idx = t; idx < 16 * CH; idx += 1024) {
        int i = idx >> 7, k = idx & 127;
        Whs[i*132 + k] = w_in[(h*16 + i)*CH + k] * g_alpha[b][k];
    }
    CP_WAIT0();
    __syncthreads();

    {
        int l = t >> 3, i0 = t & 7;
        float ta0 = 0.f, ta1 = 0.f;
        #pragma unroll 4
        for (int k4 = 0; k4 < 32; ++k4) {
            float4 sv = *(const float4*)&Ss[l*132 + 4*k4];
            float4 w0 = *(const float4*)&Whs[i0*132 + 4*k4];
            float4 w1 = *(const float4*)&Whs[(i0 + 8)*132 + 4*k4];
            ta0 += w0.x*sv.x + w0.y*sv.y + w0.z*sv.z + w0.w*sv.w;
            ta1 += w1.x*sv.x + w1.y*sv.y + w1.z*sv.z + w1.w*sv.w;
        }
        Ts[i0*132 + l]       = ta0;
        Ts[(i0 + 8)*132 + l] = ta1;
    }
    __syncthreads();

    if (t < 256) {
        int i = t >> 4, j = t & 15;
        float g = 0.f;
        #pragma unroll 4
        for (int l4 = 0; l4 < 32; ++l4) {
            float4 tv = *(const float4*)&Ts[i*132 + 4*l4];
            float4 wv = *(const float4*)&Whs[j*132 + 4*l4];
            g += tv.x*wv.x + tv.y*wv.y + tv.z*wv.z + tv.w*wv.w;
        }
        float ui = g_u[b][h*16 + i], bi = g_Bp[b][h*16 + i];
        float uj = g_u[b][h*16 + j], bj = g_Bp[b][h*16 + j];
        sc[i*17 + j] = 0.25f * (g + ui*bj + bi*uj + (float)SP * bi * bj);
    }
    __syncthreads();

    if (t < 16) {
        float m = sc[t*17 + 0];
        #pragma unroll
        for (int j = 1; j < 16; ++j) m = fmaxf(m, sc[t*17 + j]);
        float e[16], s = 0.f;
        #pragma unroll
        for (int j = 0; j < 16; ++j) { e[j] = expf(sc[t*17 + j] - m); s += e[j]; }
        float inv = 1.f / s;
        #pragma unroll
        for (int j = 0; j < 16; ++j) Wt[t*17 + j] = e[j] * inv;
    }
    __syncthreads();

    {
        int o = t >> 3, j0 = (t & 7) * 2;
        float m0 = 0.f, m1 = 0.f;
        const float* wrow = w_out + o*CH + h*16;
        #pragma unroll
        for (int i = 0; i < 16; ++i) {
            float wo = wrow[i];
            m0 += wo * Wt[i*17 + j0];
            m1 += wo * Wt[i*17 + j0 + 1];
        }
        g_M[b][o][h*16 + j0]     = m0;
        g_M[b][o][h*16 + j0 + 1] = m1;
    }
}

// ===== prep3: A = (M W' + I) bf16 hi/lo [o][c]; d = M B' + b_out (8 rows/blk) ==
__global__ __launch_bounds__(128) void k_prep3(const float* __restrict__ w_in,
                                               const float* __restrict__ b_out) {
    int b = blockIdx.y, o0 = blockIdx.x * 8;
    int t = threadIdx.x;  // = c
    __shared__ float Ms[8][CH];
    __shared__ float Bp_s[CH];
    for (int idx = t; idx < 8 * CH; idx += 128) {
        int i = idx >> 7, k = idx & 127;
        Ms[i][k] = g_M[b][o0 + i][k];
    }
    Bp_s[t] = g_Bp[b][t];
    __syncthreads();
    float a[8];
    #pragma unroll
    for (int i = 0; i < 8; ++i) a[i] = 0.f;
    for (int k = 0; k < CH; ++k) {
        float wv = w_in[k * CH + t];
        #pragma unroll
        for (int i = 0; i < 8; ++i) a[i] += Ms[i][k] * wv;
    }
    float al = g_alpha[b][t];
    #pragma unroll
    for (int i = 0; i < 8; ++i) {
        float v = al * a[i];
        if (o0 + i == t) v += 1.0f;
        __nv_bfloat16 hh = __float2bfloat16(v);
        g_Ahi[b][(o0 + i) * CH + t] = hh;
        g_Alo[b][(o0 + i) * CH + t] = __float2bfloat16(v - __bfloat162float(hh));
    }
    if (t < 8) {
        float dv = b_out[o0 + t];
        for (int k = 0; k < CH; ++k) dv += Ms[t][k] * Bp_s[k];
        g_d[b][o0 + t] = dv;
    }
}

// ====== main: out = (C+I) x + d via HMMA; single X buffer, occupancy 2 ======
#define MB_AH  0                     // 128 x 272 B
#define MB_AL  34816
#define MB_XH  69632                 // 128 x 144 B
#define MB_XL  88064
#define MB_DS  106496
#define MB_SMEM 107008
#define MB_NT 7
#define MB_BX 37
__global__ __launch_bounds__(256, 2) void k_main_mma4(float* __restrict__ out) {
    extern __shared__ __align__(16) char sm[];
    uint32_t sb = smem_u32(sm);
    int b = blockIdx.y, bx = blockIdx.x;
    int t = threadIdx.x;
    int wid = t >> 5, lane = t & 31, g = lane >> 2, tg = lane & 3;
    int m0 = (wid >> 1) * 32, n0 = (wid & 1) * 32;

    uint32_t aBase0 = (uint32_t)(m0 + (lane & 15)) * 272 + (lane >> 4) * 16;
    uint32_t aBase1 = aBase0 + 16 * 272;
    uint32_t bTr = (uint32_t)((lane & 7) + ((lane >> 3) & 1) * 8) * 144 + n0 * 2;

    const __nv_bfloat16* xh = g_xh + (size_t)b * BSTRIDE;
    const __nv_bfloat16* xl = g_xl + (size_t)b * BSTRIDE;
    float* ob = out + (size_t)b * BSTRIDE;
    const float* ds = (const float*)(sm + MB_DS);

    // prologue: A hi/lo + d (group 0)
    {
        const char* Ah = (const char*)&g_Ahi[b][0];
        const char* Al = (const char*)&g_Alo[b][0];
        #pragma unroll
        for (int w = 0; w < 8; ++w) {
            int m = t + 256*w;
            int o = m >> 4, cg = m & 15;
            uint32_t doff = (uint32_t)o*272 + cg*16;
            CP_ASYNC16(sb + MB_AH + doff, Ah + m*16);
            CP_ASYNC16(sb + MB_AL + doff, Al + m*16);
        }
        if (t < 32) CP_ASYNC16(sb + MB_DS + t*16, (const char*)&g_d[b][0] + t*16);
        CP_COMMIT();
    }

    for (int it = 0; it < MB_NT; ++it) {
        int st = bx + MB_BX*it;
        bool valid = st < 256;
        int stc = valid ? st : 255;
        __syncthreads();                 // prev iter's mma done reading X buffer
        #pragma unroll
        for (int w = 0; w < 4; ++w) {
            int m = t + 256*w;           // 1024 chunks per array
            int row = m >> 3, c16 = m & 7;
            uint32_t doff = (uint32_t)row*144 + c16*16;
            CP_ASYNC16(sb + MB_XH + doff, xh + (size_t)row*SP + stc*64 + c16*8);
            CP_ASYNC16(sb + MB_XL + doff, xl + (size_t)row*SP + stc*64 + c16*8);
        }
        CP_COMMIT();
        CP_WAIT0();
        __syncthreads();

        float acc[2][4][4];
        #pragma unroll
        for (int i = 0; i < 2; ++i)
            #pragma unroll
            for (int j = 0; j < 4; ++j)
                #pragma unroll
                for (int q = 0; q < 4; ++q) acc[i][j][q] = 0.f;

        #pragma unroll
        for (int k = 0; k < 8; ++k) {
            uint32_t koffA = k * 32;
            uint32_t koffX = k * 16 * 144;
            uint32_t ah[2][4], al[2][4];
            ldmx4(ah[0], sb + MB_AH + aBase0 + koffA);
            ldmx4(ah[1], sb + MB_AH + aBase1 + koffA);
            ldmx4(al[0], sb + MB_AL + aBase0 + koffA);
            ldmx4(al[1], sb + MB_AL + aBase1 + koffA);
            #pragma unroll
            for (int j = 0; j < 4; ++j) {
                uint32_t bh[2], bl[2];
                ldmx2t(bh, sb + MB_XH + bTr + koffX + j*16);
                ldmx2t(bl, sb + MB_XL + bTr + koffX + j*16);
                #pragma unroll
                for (int i = 0; i < 2; ++i) {
                    mma16816(acc[i][j], ah[i][0], ah[i][1], ah[i][2], ah[i][3], bh[0], bh[1]);
                    mma16816(acc[i][j], ah[i][0], ah[i][1], ah[i][2], ah[i][3], bl[0], bl[1]);
                    mma16816(acc[i][j], al[i][0], al[i][1], al[i][2], al[i][3], bh[0], bh[1]);
                }
            }
        }

        if (valid) {
            int s0 = st * 64;
            #pragma unroll
            for (int i = 0; i < 2; ++i) {
                int r0 = m0 + 16*i + g, r1 = r0 + 8;
                float d0 = ds[r0], d1 = ds[r1];
                #pragma unroll
                for (int j = 0; j < 4; ++j) {
                    int scol = s0 + n0 + 8*j + 2*tg;
                    float2 v0 = { acc[i][j][0] + d0, acc[i][j][1] + d0 };
                    float2 v1 = { acc[i][j][2] + d1, acc[i][j][3] + d1 };
                    *(float2*)(ob + (size_t)r0 * SP + scol) = v0;
                    *(float2*)(ob + (size_t)r1 * SP + scol) = v1;
                }
            }
        }
    }
}

extern "C" void kernel_launch(void* const* d_in, const int* in_sizes, int n_in,
                              void* d_out, int out_size) {
    const float* x    = (const float*)d_in[0];
    const float* gn_w = (const float*)d_in[1];
    const float* gn_b = (const float*)d_in[2];
    const float* w_in = (const float*)d_in[3];
    const float* b_in = (const float*)d_in[4];
    const float* w_out= (const float*)d_in[5];
    const float* b_out= (const float*)d_in[6];
    float* out = (float*)d_out;
    (void)in_sizes; (void)n_in; (void)out_size;

    cudaFuncSetAttribute(k_syrk_conv, cudaFuncAttributeMaxDynamicSharedMemorySize, SK_SMEM);
    cudaFuncSetAttribute(k_prep2,     cudaFuncAttributeMaxDynamicSharedMemorySize, P2_SMEM);
    cudaFuncSetAttribute(k_main_mma4, cudaFuncAttributeMaxDynamicSharedMemorySize, MB_SMEM);

    k_zero<<<NB * CH * CH / 256, 256>>>();
    k_syrk_conv<<<dim3(32, NB), 256, SK_SMEM>>>(x);
    k_prep1<<<NB, 512>>>(gn_w, gn_b, w_in, b_in);
    k_prep2<<<64, 1024, P2_SMEM>>>(w_in, w_out);
    k_prep3<<<dim3(16, NB), 128>>>(w_in, b_out);
    k_main_mma4<<<dim3(MB_BX, NB), 256, MB_SMEM>>>(out);
}